// round 14
// baseline (speedup 1.0000x reference)
#include <cuda_runtime.h>
#include <cuda_bf16.h>
#include <math.h>
#include <stdint.h>

#define NQ 1024
#define NB 8
#define MM 1024
#define CC 640
#define RR 8192
#define NITER 100
#define EPS_INV 20.0f
#define NU_P (1.0f/1024.0f + 1e-8f)

__device__ float g_q[RR*CC];
__device__ float g_k[RR*CC];
__device__ float g_v[RR*CC];
__device__ float g_x[RR*CC];
__device__ float g_sim[NB*MM*NQ];
__device__ float g_E[NB*MM*NQ];
__device__ __nv_bfloat16 g_Ebf[NB*MM*NQ];
__device__ float g_cpart[128*NQ];
__device__ float g_a[RR];
__device__ float g_mu[RR];
__device__ float g_bfin[RR];
__device__ unsigned char g_maskb[RR];
__device__ int g_counts[NB];
__device__ int g_mfmt;
__device__ unsigned int g_flag[128];
__device__ __nv_bfloat16 g_qs0[RR*CC];
__device__ __nv_bfloat16 g_qs1[RR*CC];
__device__ __nv_bfloat16 g_ks0[RR*CC];
__device__ __nv_bfloat16 g_ks1[RR*CC];

__device__ __forceinline__ int getmask_raw(const void* m, int idx, int fmt) {
    if (fmt == 1) return ((const int*)m)[idx] != 0;
    if (fmt == 2) return ((const float*)m)[idx] != 0.0f;
    return ((const unsigned char*)m)[idx] != 0;
}

__global__ void k_detect(const unsigned char* m) {
    __shared__ int cA, cB;
    if (threadIdx.x == 0) { cA = 0; cB = 0; }
    __syncthreads();
    int a = 0, b = 0;
    for (int i = threadIdx.x; i < RR; i += blockDim.x) {
        if (m[i] != 0) { if ((i & 3) == 0) a = 1; else b = 1; }
    }
    if (a) atomicOr(&cA, 1);
    if (b) atomicOr(&cB, 1);
    __syncthreads();
    if (threadIdx.x == 0) g_mfmt = (cB == 0) ? 1 : ((cA == 0) ? 2 : 0);
}

__global__ void k_counts(const void* mask) {
    __shared__ int sh[256];
    int fmt = g_mfmt, bb = blockIdx.x, s = 0;
    for (int m = threadIdx.x; m < MM; m += 256) s += getmask_raw(mask, bb*MM + m, fmt);
    sh[threadIdx.x] = s; __syncthreads();
    for (int o = 128; o; o >>= 1) { if (threadIdx.x < o) sh[threadIdx.x] += sh[threadIdx.x + o]; __syncthreads(); }
    if (threadIdx.x == 0) g_counts[bb] = (sh[0] > 0) ? sh[0] : 1;
}

__global__ void k_init(const void* mask) {
    int idx = blockIdx.x * blockDim.x + threadIdx.x;
    if (idx < 128) g_flag[idx] = 0u;
    if (idx < RR) {
        int fmt = g_mfmt;
        int mk = getmask_raw(mask, idx, fmt);
        g_maskb[idx] = (unsigned char)mk;
        g_mu[idx] = mk ? (1.0f/(float)g_counts[idx >> 10] + 1e-8f) : 0.0f;
    }
}

__global__ void k_l2split(const float* __restrict__ src,
                          __nv_bfloat16* __restrict__ d0,
                          __nv_bfloat16* __restrict__ d1) {
    __shared__ float sh[256];
    const float* row = src + (size_t)blockIdx.x * CC;
    float s = 0.0f;
    for (int i = threadIdx.x; i < CC; i += 256) { float v = row[i]; s += v*v; }
    sh[threadIdx.x] = s; __syncthreads();
    for (int o = 128; o; o >>= 1) { if (threadIdx.x < o) sh[threadIdx.x] += sh[threadIdx.x + o]; __syncthreads(); }
    float inv = 1.0f / fmaxf(sqrtf(sh[0]), 1e-12f);
    size_t base = (size_t)blockIdx.x * CC;
    for (int i = threadIdx.x; i < CC; i += 256) {
        float x = row[i] * inv;
        __nv_bfloat16 b0 = __float2bfloat16(x);
        float r = x - __bfloat162float(b0);
        d0[base + i] = b0; d1[base + i] = __float2bfloat16(r);
    }
}

__device__ __forceinline__ void split8_store(float4 v0, float4 v1,
                                             __nv_bfloat16* dhi, __nv_bfloat16* dlo) {
    float f[8] = {v0.x, v0.y, v0.z, v0.w, v1.x, v1.y, v1.z, v1.w};
    uint32_t hw[4], lw[4];
    #pragma unroll
    for (int i = 0; i < 4; i++) {
        __nv_bfloat16 h0 = __float2bfloat16(f[2*i]);
        __nv_bfloat16 h1 = __float2bfloat16(f[2*i+1]);
        __nv_bfloat162 hp = __halves2bfloat162(h0, h1);
        hw[i] = *(uint32_t*)&hp;
        __nv_bfloat16 l0 = __float2bfloat16(f[2*i]   - __bfloat162float(h0));
        __nv_bfloat16 l1 = __float2bfloat16(f[2*i+1] - __bfloat162float(h1));
        __nv_bfloat162 lp = __halves2bfloat162(l0, l1);
        lw[i] = *(uint32_t*)&lp;
    }
    *(uint4*)dhi = make_uint4(hw[0], hw[1], hw[2], hw[3]);
    *(uint4*)dlo = make_uint4(lw[0], lw[1], lw[2], lw[3]);
}

// ---- pipelined chunk-32 double-buffered smem layout ----
#define SPAD 40
#define BOFF (4*128*SPAD)
#define ASP(b,s,r,c) dyn[(((b)*2+(s))*128 + (r))*SPAD + (c)]
#define BSP(b,s,r,c) dyn[BOFF + (((b)*2+(s))*128 + (r))*SPAD + (c)]
#define DYN_BYTES (2*BOFF*2)

#define MMA_FRAGS_P(B) \
    uint32_t af[2][4][4], bfr[2][4][2]; \
    _Pragma("unroll") \
    for (int s = 0; s < 2; s++) { \
        _Pragma("unroll") \
        for (int mi = 0; mi < 4; mi++) { \
            int r0 = wm + mi*16 + g; \
            af[s][mi][0] = *(const uint32_t*)&ASP(B, s, r0,   kk + tg*2); \
            af[s][mi][1] = *(const uint32_t*)&ASP(B, s, r0+8, kk + tg*2); \
            af[s][mi][2] = *(const uint32_t*)&ASP(B, s, r0,   kk + tg*2 + 8); \
            af[s][mi][3] = *(const uint32_t*)&ASP(B, s, r0+8, kk + tg*2 + 8); \
        } \
        _Pragma("unroll") \
        for (int ni = 0; ni < 4; ni++) { \
            int c0 = wn + ni*8 + g; \
            bfr[s][ni][0] = *(const uint32_t*)&BSP(B, s, c0, kk + tg*2); \
            bfr[s][ni][1] = *(const uint32_t*)&BSP(B, s, c0, kk + tg*2 + 8); \
        } \
    } \
    _Pragma("unroll") \
    for (int p = 0; p < 3; p++) { \
        const int sa = (p == 2) ? 1 : 0, sb = (p == 1) ? 1 : 0; \
        _Pragma("unroll") \
        for (int mi = 0; mi < 4; mi++) \
            _Pragma("unroll") \
            for (int ni = 0; ni < 4; ni++) \
                asm volatile( \
                    "mma.sync.aligned.m16n8k16.row.col.f32.bf16.bf16.f32 " \
                    "{%0,%1,%2,%3}, {%4,%5,%6,%7}, {%8,%9}, {%0,%1,%2,%3};" \
                    : "+f"(acc[mi][ni][0]), "+f"(acc[mi][ni][1]), \
                      "+f"(acc[mi][ni][2]), "+f"(acc[mi][ni][3]) \
                    : "r"(af[sa][mi][0]), "r"(af[sa][mi][1]), \
                      "r"(af[sa][mi][2]), "r"(af[sa][mi][3]), \
                      "r"(bfr[sb][ni][0]), "r"(bfr[sb][ni][1])); \
    }

__device__ __forceinline__ void gemm_body(const float* __restrict__ A,
                                          const float* __restrict__ B,
                                          const float* __restrict__ bias,
                                          float* __restrict__ Co,
                                          __nv_bfloat16* dyn) {
    const int tid = threadIdx.x, warp = tid >> 5, lane = tid & 31;
    const int g = lane >> 2, tg = lane & 3;
    const int i0 = blockIdx.x * 128, j0 = blockIdx.y * 128;
    const int wm = (warp & 1) * 64, wn = (warp >> 1) * 32;
    float acc[4][4][4];
    #pragma unroll
    for (int mi = 0; mi < 4; mi++)
        #pragma unroll
        for (int ni = 0; ni < 4; ni++)
            #pragma unroll
            for (int e = 0; e < 4; e++) acc[mi][ni][e] = 0.0f;
    const int lrow = tid >> 1, half = tid & 1;
    const float* Abase = A + (size_t)(i0 + lrow) * CC;
    const float* Bbase = B + (size_t)(j0 + lrow) * CC;
    #pragma unroll
    for (int u = 0; u < 2; u++) {
        int seg = half*2 + u;
        split8_store(*(const float4*)(Abase + seg*8), *(const float4*)(Abase + seg*8 + 4),
                     &ASP(0,0,lrow,seg*8), &ASP(0,1,lrow,seg*8));
        split8_store(*(const float4*)(Bbase + seg*8), *(const float4*)(Bbase + seg*8 + 4),
                     &BSP(0,0,lrow,seg*8), &BSP(0,1,lrow,seg*8));
    }
    __syncthreads();
    const int NCH = CC/32;
    for (int ci = 0; ci < NCH; ci++) {
        const int cur = ci & 1;
        float4 ra[4], rb[4];
        if (ci + 1 < NCH) {
            int k0 = (ci+1)*32;
            #pragma unroll
            for (int u = 0; u < 2; u++) {
                int seg = half*2 + u;
                ra[2*u+0] = *(const float4*)(Abase + k0 + seg*8);
                ra[2*u+1] = *(const float4*)(Abase + k0 + seg*8 + 4);
                rb[2*u+0] = *(const float4*)(Bbase + k0 + seg*8);
                rb[2*u+1] = *(const float4*)(Bbase + k0 + seg*8 + 4);
            }
        }
        #pragma unroll
        for (int kk = 0; kk < 32; kk += 16) { MMA_FRAGS_P(cur) }
        if (ci + 1 < NCH) {
            int nb = cur ^ 1;
            #pragma unroll
            for (int u = 0; u < 2; u++) {
                int seg = half*2 + u;
                split8_store(ra[2*u], ra[2*u+1], &ASP(nb,0,lrow,seg*8), &ASP(nb,1,lrow,seg*8));
                split8_store(rb[2*u], rb[2*u+1], &BSP(nb,0,lrow,seg*8), &BSP(nb,1,lrow,seg*8));
            }
        }
        __syncthreads();
    }
    #pragma unroll
    for (int mi = 0; mi < 4; mi++) {
        int r0 = i0 + wm + mi*16 + g;
        #pragma unroll
        for (int ni = 0; ni < 4; ni++) {
            int c = j0 + wn + ni*8 + tg*2;
            float b0v = bias[c], b1v = bias[c+1];
            Co[(size_t)r0*CC + c]       = acc[mi][ni][0] + b0v;
            Co[(size_t)r0*CC + c+1]     = acc[mi][ni][1] + b1v;
            Co[(size_t)(r0+8)*CC + c]   = acc[mi][ni][2] + b0v;
            Co[(size_t)(r0+8)*CC + c+1] = acc[mi][ni][3] + b1v;
        }
    }
}

__global__ __launch_bounds__(256) void k_gemm3(
    const float* xq, const float* Wq, const float* bq, float* oq,
    const float* xk, const float* Wk, const float* bk, float* ok,
    const float* xv, const float* Wv, const float* bv, float* ov) {
    extern __shared__ __nv_bfloat16 dyn[];
    if (blockIdx.z == 0)      gemm_body(xq, Wq, bq, oq, dyn);
    else if (blockIdx.z == 1) gemm_body(xk, Wk, bk, ok, dyn);
    else                      gemm_body(xv, Wv, bv, ov, dyn);
}

__global__ __launch_bounds__(256) void k_gemm1(
    const float* A, const float* B, const float* bias, float* Co) {
    extern __shared__ __nv_bfloat16 dyn[];
    gemm_body(A, B, bias, Co, dyn);
}

__global__ __launch_bounds__(256) void k_simE_mma() {
    extern __shared__ __nv_bfloat16 dyn[];
    const int tid = threadIdx.x, warp = tid >> 5, lane = tid & 31;
    const int g = lane >> 2, tg = lane & 3;
    const int bb = blockIdx.z, m0 = blockIdx.x * 128, n0 = blockIdx.y * 128;
    const int wm = (warp & 1) * 64, wn = (warp >> 1) * 32;
    float acc[4][4][4];
    #pragma unroll
    for (int mi = 0; mi < 4; mi++)
        #pragma unroll
        for (int ni = 0; ni < 4; ni++)
            #pragma unroll
            for (int e = 0; e < 4; e++) acc[mi][ni][e] = 0.0f;
    const int lrow = tid >> 1, half = tid & 1;
    const __nv_bfloat16* K0 = g_ks0 + (size_t)(bb*MM + m0 + lrow) * CC;
    const __nv_bfloat16* K1 = g_ks1 + (size_t)(bb*MM + m0 + lrow) * CC;
    const __nv_bfloat16* Q0 = g_qs0 + ((size_t)(n0 + lrow)*NB + bb) * CC;
    const __nv_bfloat16* Q1 = g_qs1 + ((size_t)(n0 + lrow)*NB + bb) * CC;
    #pragma unroll
    for (int u = 0; u < 2; u++) {
        int seg = half*2 + u;
        *(uint4*)&ASP(0,0,lrow,seg*8) = *(const uint4*)(K0 + seg*8);
        *(uint4*)&ASP(0,1,lrow,seg*8) = *(const uint4*)(K1 + seg*8);
        *(uint4*)&BSP(0,0,lrow,seg*8) = *(const uint4*)(Q0 + seg*8);
        *(uint4*)&BSP(0,1,lrow,seg*8) = *(const uint4*)(Q1 + seg*8);
    }
    __syncthreads();
    const int NCH = CC/32;
    for (int ci = 0; ci < NCH; ci++) {
        const int cur = ci & 1;
        uint4 rk0[2], rk1[2], rq0[2], rq1[2];
        if (ci + 1 < NCH) {
            int k0 = (ci+1)*32;
            #pragma unroll
            for (int u = 0; u < 2; u++) {
                int seg = half*2 + u;
                rk0[u] = *(const uint4*)(K0 + k0 + seg*8);
                rk1[u] = *(const uint4*)(K1 + k0 + seg*8);
                rq0[u] = *(const uint4*)(Q0 + k0 + seg*8);
                rq1[u] = *(const uint4*)(Q1 + k0 + seg*8);
            }
        }
        #pragma unroll
        for (int kk = 0; kk < 32; kk += 16) { MMA_FRAGS_P(cur) }
        if (ci + 1 < NCH) {
            int nb = cur ^ 1;
            #pragma unroll
            for (int u = 0; u < 2; u++) {
                int seg = half*2 + u;
                *(uint4*)&ASP(nb,0,lrow,seg*8) = rk0[u];
                *(uint4*)&ASP(nb,1,lrow,seg*8) = rk1[u];
                *(uint4*)&BSP(nb,0,lrow,seg*8) = rq0[u];
                *(uint4*)&BSP(nb,1,lrow,seg*8) = rq1[u];
            }
        }
        __syncthreads();
    }
    #pragma unroll
    for (int mi = 0; mi < 4; mi++) {
        int mA = m0 + wm + mi*16 + g;
        int mB = mA + 8;
        int mkA = g_maskb[bb*MM + mA], mkB = g_maskb[bb*MM + mB];
        size_t baseA = ((size_t)bb*MM + mA) * NQ;
        size_t baseB = ((size_t)bb*MM + mB) * NQ;
        #pragma unroll
        for (int ni = 0; ni < 4; ni++) {
            int c = n0 + wn + ni*8 + tg*2;
            float s0 = acc[mi][ni][0], s1 = acc[mi][ni][1];
            float s2 = acc[mi][ni][2], s3 = acc[mi][ni][3];
            g_sim[baseA + c]   = s0; g_sim[baseA + c+1] = s1;
            g_sim[baseB + c]   = s2; g_sim[baseB + c+1] = s3;
            float e0 = mkA ? expf((s0 - 1.0f) * EPS_INV) : 0.0f;
            float e1 = mkA ? expf((s1 - 1.0f) * EPS_INV) : 0.0f;
            float e2 = mkB ? expf((s2 - 1.0f) * EPS_INV) : 0.0f;
            float e3 = mkB ? expf((s3 - 1.0f) * EPS_INV) : 0.0f;
            g_E[baseA + c]   = e0; g_E[baseA + c+1] = e1;
            g_E[baseB + c]   = e2; g_E[baseB + c+1] = e3;
            g_Ebf[baseA + c]   = __float2bfloat16(e0);
            g_Ebf[baseA + c+1] = __float2bfloat16(e1);
            g_Ebf[baseB + c]   = __float2bfloat16(e2);
            g_Ebf[baseB + c+1] = __float2bfloat16(e3);
        }
    }
}

// HMMA TN xgemm (unchanged)
#define MMA_FRAGS_S \
    uint32_t af[2][4][4], bfr[2][4][2]; \
    _Pragma("unroll") \
    for (int s = 0; s < 2; s++) { \
        _Pragma("unroll") \
        for (int mi = 0; mi < 4; mi++) { \
            int r0 = wm + mi*16 + g; \
            af[s][mi][0] = *(const uint32_t*)&As[s][r0][kk + tg*2]; \
            af[s][mi][1] = *(const uint32_t*)&As[s][r0+8][kk + tg*2]; \
            af[s][mi][2] = *(const uint32_t*)&As[s][r0][kk + tg*2 + 8]; \
            af[s][mi][3] = *(const uint32_t*)&As[s][r0+8][kk + tg*2 + 8]; \
        } \
        _Pragma("unroll") \
        for (int ni = 0; ni < 4; ni++) { \
            int c0 = wn + ni*8 + g; \
            bfr[s][ni][0] = *(const uint32_t*)&Bs[s][c0][kk + tg*2]; \
            bfr[s][ni][1] = *(const uint32_t*)&Bs[s][c0][kk + tg*2 + 8]; \
        } \
    } \
    _Pragma("unroll") \
    for (int p = 0; p < 3; p++) { \
        const int sa = (p == 2) ? 1 : 0, sb = (p == 1) ? 1 : 0; \
        _Pragma("unroll") \
        for (int mi = 0; mi < 4; mi++) \
            _Pragma("unroll") \
            for (int ni = 0; ni < 4; ni++) \
                asm volatile( \
                    "mma.sync.aligned.m16n8k16.row.col.f32.bf16.bf16.f32 " \
                    "{%0,%1,%2,%3}, {%4,%5,%6,%7}, {%8,%9}, {%0,%1,%2,%3};" \
                    : "+f"(acc[mi][ni][0]), "+f"(acc[mi][ni][1]), \
                      "+f"(acc[mi][ni][2]), "+f"(acc[mi][ni][3]) \
                    : "r"(af[sa][mi][0]), "r"(af[sa][mi][1]), \
                      "r"(af[sa][mi][2]), "r"(af[sa][mi][3]), \
                      "r"(bfr[sb][ni][0]), "r"(bfr[sb][ni][1])); \
    }

__global__ __launch_bounds__(256) void k_xgemm_mma() {
    __shared__ __nv_bfloat16 As[2][128][SPAD];
    __shared__ __nv_bfloat16 Bs[2][128][SPAD];
    const int tid = threadIdx.x, warp = tid >> 5, lane = tid & 31;
    const int g = lane >> 2, tg = lane & 3;
    const int bb = blockIdx.z, n0 = blockIdx.x * 128, c0 = blockIdx.y * 128;
    const int wm = (warp & 1) * 64, wn = (warp >> 1) * 32;
    float acc[4][4][4];
    #pragma unroll
    for (int mi = 0; mi < 4; mi++)
        #pragma unroll
        for (int ni = 0; ni < 4; ni++)
            #pragma unroll
            for (int e = 0; e < 4; e++) acc[mi][ni][e] = 0.0f;
    const float* Eb = g_E + (size_t)bb*MM*NQ;
    const float* Vb = g_v + (size_t)bb*MM*CC;
    const int lm = tid & 31, lg = tid >> 5;
    for (int k0 = 0; k0 < MM; k0 += 32) {
        int m = k0 + lm;
        float am = g_a[bb*MM + m];
        #pragma unroll
        for (int j = 0; j < 4; j++) {
            int n = lg*16 + j*4;
            float4 ev = *(const float4*)(Eb + (size_t)m*NQ + n0 + n);
            float4 vv = *(const float4*)(Vb + (size_t)m*CC + c0 + n);
            vv.x *= am; vv.y *= am; vv.z *= am; vv.w *= am;
            float ee[4] = {ev.x, ev.y, ev.z, ev.w};
            float va[4] = {vv.x, vv.y, vv.z, vv.w};
            #pragma unroll
            for (int q = 0; q < 4; q++) {
                __nv_bfloat16 h = __float2bfloat16(ee[q]);
                As[0][n + q][lm] = h;
                As[1][n + q][lm] = __float2bfloat16(ee[q] - __bfloat162float(h));
                __nv_bfloat16 hv = __float2bfloat16(va[q]);
                Bs[0][n + q][lm] = hv;
                Bs[1][n + q][lm] = __float2bfloat16(va[q] - __bfloat162float(hv));
            }
        }
        __syncthreads();
        #pragma unroll
        for (int kk = 0; kk < 32; kk += 16) { MMA_FRAGS_S }
        __syncthreads();
    }
    #pragma unroll
    for (int mi = 0; mi < 4; mi++) {
        int nA = n0 + wm + mi*16 + g;
        int nB = nA + 8;
        float bnA = g_bfin[bb*NQ + nA], bnB = g_bfin[bb*NQ + nB];
        #pragma unroll
        for (int ni = 0; ni < 4; ni++) {
            int c = c0 + wn + ni*8 + tg*2;
            g_x[((size_t)nA*NB + bb)*CC + c]   = acc[mi][ni][0] * bnA;
            g_x[((size_t)nA*NB + bb)*CC + c+1] = acc[mi][ni][1] * bnA;
            g_x[((size_t)nB*NB + bb)*CC + c]   = acc[mi][ni][2] * bnB;
            g_x[((size_t)nB*NB + bb)*CC + c+1] = acc[mi][ni][3] * bnB;
        }
    }
}

// persistent Sinkhorn: smem E, flag barrier, fused attn epilogue
#define SINK_SMEM (64*NQ*2 + 8*NQ*4)
__global__ __launch_bounds__(256) void k_sink_pers(float* attn_out) {
    extern __shared__ char dsm[];
    __nv_bfloat16* Es = (__nv_bfloat16*)dsm;
    float* shred = (float*)(dsm + 64*NQ*2);
    const int blk = blockIdx.x, bb = blk >> 4, rb = blk & 15;
    const int tid = threadIdx.x, warp = tid >> 5, lane = tid & 31;
    const int col = tid * 4;
    {
        const uint4* src = (const uint4*)(g_Ebf + ((size_t)bb*MM + rb*64) * NQ);
        uint4* dst = (uint4*)Es;
        for (int i = tid; i < 64*NQ/8; i += 256) dst[i] = src[i];
    }
    __syncthreads();
    float bv[32];
    #pragma unroll
    for (int q = 0; q < 32; q++) bv[q] = 1.0f;
    float a_loc[8];
    #pragma unroll
    for (int q = 0; q < 8; q++) a_loc[q] = 0.0f;
    volatile unsigned int* flags = (volatile unsigned int*)g_flag;
    for (int it = 1; it <= NITER; it++) {
        float cacc[32];
        #pragma unroll
        for (int q = 0; q < 32; q++) cacc[q] = 0.0f;
        #pragma unroll
        for (int rr = 0; rr < 8; rr++) {
            int lr = warp*8 + rr;
            int m = rb*64 + lr;
            if (!g_maskb[bb*MM + m]) {
                if (it == NITER && lane == 0) g_a[bb*MM + m] = 0.0f;
                continue;
            }
            const __nv_bfloat16* er = Es + (size_t)lr * NQ;
            float e[32], s = 0.0f;
            #pragma unroll
            for (int g = 0; g < 8; g++) {
                uint2 w = *(const uint2*)(er + g*128 + lane*4);
                __nv_bfloat162 p0 = *(__nv_bfloat162*)&w.x;
                __nv_bfloat162 p1 = *(__nv_bfloat162*)&w.y;
                e[g*4+0] = __bfloat162float(__low2bfloat16(p0));
                e[g*4+1] = __bfloat162float(__high2bfloat16(p0));
                e[g*4+2] = __bfloat162float(__low2bfloat16(p1));
                e[g*4+3] = __bfloat162float(__high2bfloat16(p1));
                s += e[g*4+0]*bv[g*4+0] + e[g*4+1]*bv[g*4+1]
                   + e[g*4+2]*bv[g*4+2] + e[g*4+3]*bv[g*4+3];
            }
            #pragma unroll
            for (int o = 16; o; o >>= 1) s += __shfl_xor_sync(0xffffffffu, s, o);
            float a = g_mu[bb*MM + m] / s;
            if (it == NITER) {
                a_loc[rr] = a;
                if (lane == 0) g_a[bb*MM + m] = a;
            }
            #pragma unroll
            for (int q = 0; q < 32; q++) cacc[q] += a * e[q];
        }
        #pragma unroll
        for (int g = 0; g < 8; g++)
            *(float4*)&shred[warp*1024 + g*128 + lane*4] =
                make_float4(cacc[g*4], cacc[g*4+1], cacc[g*4+2], cacc[g*4+3]);
        __syncthreads();
        float s0=0, s1=0, s2=0, s3=0;
        #pragma unroll
        for (int w = 0; w < 8; w++) {
            float4 v = *(const float4*)&shred[w*1024 + col];
            s0 += v.x; s1 += v.y; s2 += v.z; s3 += v.w;
        }
        *(float4*)&g_cpart[(size_t)blk*NQ + col] = make_float4(s0, s1, s2, s3);
        // flag barrier: publish, then 16 threads poll the batch's 16 flags
        __threadfence();
        __syncthreads();
        if (tid == 0) flags[blk] = (unsigned int)it;
        if (tid < 16) {
            while (flags[bb*16 + tid] < (unsigned int)it) { }
        }
        __syncthreads();
        __threadfence();
        if (it < NITER) {
            float c0=0, c1=0, c2=0, c3=0;
            #pragma unroll
            for (int w = 0; w < 16; w++) {
                float4 v = *(const float4*)&g_cpart[(size_t)(bb*16 + w)*NQ + col];
                c0 += v.x; c1 += v.y; c2 += v.z; c3 += v.w;
            }
            shred[col+0] = NU_P / c0; shred[col+1] = NU_P / c1;
            shred[col+2] = NU_P / c2; shred[col+3] = NU_P / c3;
            __syncthreads();
            #pragma unroll
            for (int g = 0; g < 8; g++) {
                float4 v = *(const float4*)&shred[g*128 + lane*4];
                bv[g*4+0]=v.x; bv[g*4+1]=v.y; bv[g*4+2]=v.z; bv[g*4+3]=v.w;
            }
            __syncthreads();
        }
    }
    // final b (all blocks compute into shred; rb==0 also writes g_bfin)
    {
        float c0=0, c1=0, c2=0, c3=0;
        #pragma unroll
        for (int w = 0; w < 16; w++) {
            float4 v = *(const float4*)&g_cpart[(size_t)(bb*16 + w)*NQ + col];
            c0 += v.x; c1 += v.y; c2 += v.z; c3 += v.w;
        }
        float b0 = NU_P / c0, b1 = NU_P / c1, b2 = NU_P / c2, b3 = NU_P / c3;
        shred[col+0] = b0; shred[col+1] = b1; shred[col+2] = b2; shred[col+3] = b3;
        if (rb == 0) {
            g_bfin[bb*NQ+col+0] = b0; g_bfin[bb*NQ+col+1] = b1;
            g_bfin[bb*NQ+col+2] = b2; g_bfin[bb*NQ+col+3] = b3;
        }
    }
    __syncthreads();
    // fused attn: attn[b][m] = M*Nq * a_m * sum_n sim*E*b_n (E rows in smem)
    if (attn_out) {
        #pragma unroll
        for (int rr = 0; rr < 8; rr++) {
            int lr = warp*8 + rr;
            int m = rb*64 + lr;
            float aL = a_loc[rr];
            float s = 0.0f;
            if (aL != 0.0f) {
                const float* S = g_sim + ((size_t)bb*MM + m) * NQ;
                const __nv_bfloat16* er = Es + (size_t)lr * NQ;
                #pragma unroll
                for (int g = 0; g < 8; g++) {
                    int n = g*128 + lane*4;
                    float4 sv = *(const float4*)(S + n);
                    uint2 w = *(const uint2*)(er + n);
                    __nv_bfloat162 p0 = *(__nv_bfloat162*)&w.x;
                    __nv_bfloat162 p1 = *(__nv_bfloat162*)&w.y;
                    float4 bvv = *(const float4*)&shred[n];
                    s += sv.x * __bfloat162float(__low2bfloat16(p0))  * bvv.x
                       + sv.y * __bfloat162float(__high2bfloat16(p0)) * bvv.y
                       + sv.z * __bfloat162float(__low2bfloat16(p1))  * bvv.z
                       + sv.w * __bfloat162float(__high2bfloat16(p1)) * bvv.w;
                }
                #pragma unroll
                for (int o = 16; o; o >>= 1) s += __shfl_xor_sync(0xffffffffu, s, o);
            }
            if (lane == 0) attn_out[bb*MM + m] = 1048576.0f * aL * s;
        }
    }
}

extern "C" void kernel_launch(void* const* d_in, const int* in_sizes, int n_in,
                              void* d_out, int out_size) {
    const float* xq = (const float*)d_in[0];
    const float* xk = (const float*)d_in[1];
    const float* xv = (const float*)d_in[2];
    const void*  mk = d_in[3];
    const float* Wq = (const float*)d_in[4];
    const float* bq = (const float*)d_in[5];
    const float* Wk = (const float*)d_in[6];
    const float* bk = (const float*)d_in[7];
    const float* Wv = (const float*)d_in[8];
    const float* bv = (const float*)d_in[9];
    const float* Wp = (const float*)d_in[10];
    const float* bp = (const float*)d_in[11];
    float *qp, *kp, *vp, *xp;
    __nv_bfloat16 *q0, *q1, *ks0, *ks1;
    cudaGetSymbolAddress((void**)&qp, g_q);
    cudaGetSymbolAddress((void**)&kp, g_k);
    cudaGetSymbolAddress((void**)&vp, g_v);
    cudaGetSymbolAddress((void**)&xp, g_x);
    cudaGetSymbolAddress((void**)&q0, g_qs0);
    cudaGetSymbolAddress((void**)&q1, g_qs1);
    cudaGetSymbolAddress((void**)&ks0, g_ks0);
    cudaGetSymbolAddress((void**)&ks1, g_ks1);
    cudaFuncSetAttribute(k_gemm3, cudaFuncAttributeMaxDynamicSharedMemorySize, DYN_BYTES);
    cudaFuncSetAttribute(k_gemm1, cudaFuncAttributeMaxDynamicSharedMemorySize, DYN_BYTES);
    cudaFuncSetAttribute(k_simE_mma, cudaFuncAttributeMaxDynamicSharedMemorySize, DYN_BYTES);
    cudaFuncSetAttribute(k_sink_pers, cudaFuncAttributeMaxDynamicSharedMemorySize, SINK_SMEM);

    k_detect<<<1, 256>>>((const unsigned char*)mk);
    k_counts<<<NB, 256>>>(mk);
    k_init<<<(RR + 255)/256, 256>>>(mk);

    k_gemm3<<<dim3(RR/128, CC/128, 3), 256, DYN_BYTES>>>(
        xq, Wq, bq, qp, xk, Wk, bk, kp, xv, Wv, bv, vp);

    k_l2split<<<RR, 256>>>(qp, q0, q1);
    k_l2split<<<RR, 256>>>(kp, ks0, ks1);

    k_simE_mma<<<dim3(MM/128, NQ/128, NB), 256, DYN_BYTES>>>();

    float* attn_ptr = (out_size >= RR*CC + RR) ? ((float*)d_out + (size_t)RR*CC) : nullptr;
    k_sink_pers<<<128, 256, SINK_SMEM>>>(attn_ptr);

    k_xgemm_mma<<<dim3(NQ/128, CC/128, NB), 256>>>();

    k_gemm1<<<dim3(RR/128, CC/128), 256, DYN_BYTES>>>(xp, Wp, bp, (float*)d_out);
}

// round 15
// speedup vs baseline: 1.4564x; 1.4564x over previous
#include <cuda_runtime.h>
#include <cuda_bf16.h>
#include <math.h>
#include <stdint.h>

#define NQ 1024
#define NB 8
#define MM 1024
#define CC 640
#define RR 8192
#define NITER 100
#define EPS_INV 20.0f
#define NU_P (1.0f/1024.0f + 1e-8f)

__device__ float g_q[RR*CC];
__device__ float g_k[RR*CC];
__device__ float g_v[RR*CC];
__device__ float g_x[RR*CC];
__device__ float g_sim[NB*MM*NQ];
__device__ float g_E[NB*MM*NQ];
__device__ __nv_bfloat16 g_Ebf[NB*MM*NQ];
__device__ float g_cpart[128*NQ];
__device__ float g_a[RR];
__device__ float g_mu[RR];
__device__ float g_bfin[RR];
__device__ unsigned char g_maskb[RR];
__device__ int g_counts[NB];
__device__ int g_mfmt;
__device__ unsigned int g_bar8[NB];
__device__ __nv_bfloat16 g_qs0[RR*CC];
__device__ __nv_bfloat16 g_qs1[RR*CC];
__device__ __nv_bfloat16 g_ks0[RR*CC];
__device__ __nv_bfloat16 g_ks1[RR*CC];

__device__ __forceinline__ int getmask_raw(const void* m, int idx, int fmt) {
    if (fmt == 1) return ((const int*)m)[idx] != 0;
    if (fmt == 2) return ((const float*)m)[idx] != 0.0f;
    return ((const unsigned char*)m)[idx] != 0;
}

__global__ void k_detect(const unsigned char* m) {
    __shared__ int cA, cB;
    if (threadIdx.x == 0) { cA = 0; cB = 0; }
    __syncthreads();
    int a = 0, b = 0;
    for (int i = threadIdx.x; i < RR; i += blockDim.x) {
        if (m[i] != 0) { if ((i & 3) == 0) a = 1; else b = 1; }
    }
    if (a) atomicOr(&cA, 1);
    if (b) atomicOr(&cB, 1);
    __syncthreads();
    if (threadIdx.x == 0) g_mfmt = (cB == 0) ? 1 : ((cA == 0) ? 2 : 0);
}

__global__ void k_counts(const void* mask) {
    __shared__ int sh[256];
    int fmt = g_mfmt, bb = blockIdx.x, s = 0;
    for (int m = threadIdx.x; m < MM; m += 256) s += getmask_raw(mask, bb*MM + m, fmt);
    sh[threadIdx.x] = s; __syncthreads();
    for (int o = 128; o; o >>= 1) { if (threadIdx.x < o) sh[threadIdx.x] += sh[threadIdx.x + o]; __syncthreads(); }
    if (threadIdx.x == 0) g_counts[bb] = (sh[0] > 0) ? sh[0] : 1;
}

__global__ void k_init(const void* mask) {
    int idx = blockIdx.x * blockDim.x + threadIdx.x;
    if (idx < NB) g_bar8[idx] = 0u;
    if (idx < RR) {
        int fmt = g_mfmt;
        int mk = getmask_raw(mask, idx, fmt);
        g_maskb[idx] = (unsigned char)mk;
        g_mu[idx] = mk ? (1.0f/(float)g_counts[idx >> 10] + 1e-8f) : 0.0f;
    }
}

__global__ void k_l2split(const float* __restrict__ src,
                          __nv_bfloat16* __restrict__ d0,
                          __nv_bfloat16* __restrict__ d1) {
    __shared__ float sh[256];
    const float* row = src + (size_t)blockIdx.x * CC;
    float s = 0.0f;
    for (int i = threadIdx.x; i < CC; i += 256) { float v = row[i]; s += v*v; }
    sh[threadIdx.x] = s; __syncthreads();
    for (int o = 128; o; o >>= 1) { if (threadIdx.x < o) sh[threadIdx.x] += sh[threadIdx.x + o]; __syncthreads(); }
    float inv = 1.0f / fmaxf(sqrtf(sh[0]), 1e-12f);
    size_t base = (size_t)blockIdx.x * CC;
    for (int i = threadIdx.x; i < CC; i += 256) {
        float x = row[i] * inv;
        __nv_bfloat16 b0 = __float2bfloat16(x);
        float r = x - __bfloat162float(b0);
        d0[base + i] = b0; d1[base + i] = __float2bfloat16(r);
    }
}

__device__ __forceinline__ void split8_store(float4 v0, float4 v1,
                                             __nv_bfloat16* dhi, __nv_bfloat16* dlo) {
    float f[8] = {v0.x, v0.y, v0.z, v0.w, v1.x, v1.y, v1.z, v1.w};
    uint32_t hw[4], lw[4];
    #pragma unroll
    for (int i = 0; i < 4; i++) {
        __nv_bfloat16 h0 = __float2bfloat16(f[2*i]);
        __nv_bfloat16 h1 = __float2bfloat16(f[2*i+1]);
        __nv_bfloat162 hp = __halves2bfloat162(h0, h1);
        hw[i] = *(uint32_t*)&hp;
        __nv_bfloat16 l0 = __float2bfloat16(f[2*i]   - __bfloat162float(h0));
        __nv_bfloat16 l1 = __float2bfloat16(f[2*i+1] - __bfloat162float(h1));
        __nv_bfloat162 lp = __halves2bfloat162(l0, l1);
        lw[i] = *(uint32_t*)&lp;
    }
    *(uint4*)dhi = make_uint4(hw[0], hw[1], hw[2], hw[3]);
    *(uint4*)dlo = make_uint4(lw[0], lw[1], lw[2], lw[3]);
}

// ---- pipelined chunk-32 double-buffered smem layout ----
#define SPAD 40
#define BOFF (4*128*SPAD)
#define ASP(b,s,r,c) dyn[(((b)*2+(s))*128 + (r))*SPAD + (c)]
#define BSP(b,s,r,c) dyn[BOFF + (((b)*2+(s))*128 + (r))*SPAD + (c)]
#define DYN_BYTES (2*BOFF*2)

#define MMA_FRAGS_P(B) \
    uint32_t af[2][4][4], bfr[2][4][2]; \
    _Pragma("unroll") \
    for (int s = 0; s < 2; s++) { \
        _Pragma("unroll") \
        for (int mi = 0; mi < 4; mi++) { \
            int r0 = wm + mi*16 + g; \
            af[s][mi][0] = *(const uint32_t*)&ASP(B, s, r0,   kk + tg*2); \
            af[s][mi][1] = *(const uint32_t*)&ASP(B, s, r0+8, kk + tg*2); \
            af[s][mi][2] = *(const uint32_t*)&ASP(B, s, r0,   kk + tg*2 + 8); \
            af[s][mi][3] = *(const uint32_t*)&ASP(B, s, r0+8, kk + tg*2 + 8); \
        } \
        _Pragma("unroll") \
        for (int ni = 0; ni < 4; ni++) { \
            int c0 = wn + ni*8 + g; \
            bfr[s][ni][0] = *(const uint32_t*)&BSP(B, s, c0, kk + tg*2); \
            bfr[s][ni][1] = *(const uint32_t*)&BSP(B, s, c0, kk + tg*2 + 8); \
        } \
    } \
    _Pragma("unroll") \
    for (int p = 0; p < 3; p++) { \
        const int sa = (p == 2) ? 1 : 0, sb = (p == 1) ? 1 : 0; \
        _Pragma("unroll") \
        for (int mi = 0; mi < 4; mi++) \
            _Pragma("unroll") \
            for (int ni = 0; ni < 4; ni++) \
                asm volatile( \
                    "mma.sync.aligned.m16n8k16.row.col.f32.bf16.bf16.f32 " \
                    "{%0,%1,%2,%3}, {%4,%5,%6,%7}, {%8,%9}, {%0,%1,%2,%3};" \
                    : "+f"(acc[mi][ni][0]), "+f"(acc[mi][ni][1]), \
                      "+f"(acc[mi][ni][2]), "+f"(acc[mi][ni][3]) \
                    : "r"(af[sa][mi][0]), "r"(af[sa][mi][1]), \
                      "r"(af[sa][mi][2]), "r"(af[sa][mi][3]), \
                      "r"(bfr[sb][ni][0]), "r"(bfr[sb][ni][1])); \
    }

__device__ __forceinline__ void gemm_body(const float* __restrict__ A,
                                          const float* __restrict__ B,
                                          const float* __restrict__ bias,
                                          float* __restrict__ Co,
                                          __nv_bfloat16* dyn) {
    const int tid = threadIdx.x, warp = tid >> 5, lane = tid & 31;
    const int g = lane >> 2, tg = lane & 3;
    const int i0 = blockIdx.x * 128, j0 = blockIdx.y * 128;
    const int wm = (warp & 1) * 64, wn = (warp >> 1) * 32;
    float acc[4][4][4];
    #pragma unroll
    for (int mi = 0; mi < 4; mi++)
        #pragma unroll
        for (int ni = 0; ni < 4; ni++)
            #pragma unroll
            for (int e = 0; e < 4; e++) acc[mi][ni][e] = 0.0f;
    const int lrow = tid >> 1, half = tid & 1;
    const float* Abase = A + (size_t)(i0 + lrow) * CC;
    const float* Bbase = B + (size_t)(j0 + lrow) * CC;
    #pragma unroll
    for (int u = 0; u < 2; u++) {
        int seg = half*2 + u;
        split8_store(*(const float4*)(Abase + seg*8), *(const float4*)(Abase + seg*8 + 4),
                     &ASP(0,0,lrow,seg*8), &ASP(0,1,lrow,seg*8));
        split8_store(*(const float4*)(Bbase + seg*8), *(const float4*)(Bbase + seg*8 + 4),
                     &BSP(0,0,lrow,seg*8), &BSP(0,1,lrow,seg*8));
    }
    __syncthreads();
    const int NCH = CC/32;
    for (int ci = 0; ci < NCH; ci++) {
        const int cur = ci & 1;
        float4 ra[4], rb[4];
        if (ci + 1 < NCH) {
            int k0 = (ci+1)*32;
            #pragma unroll
            for (int u = 0; u < 2; u++) {
                int seg = half*2 + u;
                ra[2*u+0] = *(const float4*)(Abase + k0 + seg*8);
                ra[2*u+1] = *(const float4*)(Abase + k0 + seg*8 + 4);
                rb[2*u+0] = *(const float4*)(Bbase + k0 + seg*8);
                rb[2*u+1] = *(const float4*)(Bbase + k0 + seg*8 + 4);
            }
        }
        #pragma unroll
        for (int kk = 0; kk < 32; kk += 16) { MMA_FRAGS_P(cur) }
        if (ci + 1 < NCH) {
            int nb = cur ^ 1;
            #pragma unroll
            for (int u = 0; u < 2; u++) {
                int seg = half*2 + u;
                split8_store(ra[2*u], ra[2*u+1], &ASP(nb,0,lrow,seg*8), &ASP(nb,1,lrow,seg*8));
                split8_store(rb[2*u], rb[2*u+1], &BSP(nb,0,lrow,seg*8), &BSP(nb,1,lrow,seg*8));
            }
        }
        __syncthreads();
    }
    #pragma unroll
    for (int mi = 0; mi < 4; mi++) {
        int r0 = i0 + wm + mi*16 + g;
        #pragma unroll
        for (int ni = 0; ni < 4; ni++) {
            int c = j0 + wn + ni*8 + tg*2;
            float b0v = bias[c], b1v = bias[c+1];
            Co[(size_t)r0*CC + c]       = acc[mi][ni][0] + b0v;
            Co[(size_t)r0*CC + c+1]     = acc[mi][ni][1] + b1v;
            Co[(size_t)(r0+8)*CC + c]   = acc[mi][ni][2] + b0v;
            Co[(size_t)(r0+8)*CC + c+1] = acc[mi][ni][3] + b1v;
        }
    }
}

__global__ __launch_bounds__(256) void k_gemm3(
    const float* xq, const float* Wq, const float* bq, float* oq,
    const float* xk, const float* Wk, const float* bk, float* ok,
    const float* xv, const float* Wv, const float* bv, float* ov) {
    extern __shared__ __nv_bfloat16 dyn[];
    if (blockIdx.z == 0)      gemm_body(xq, Wq, bq, oq, dyn);
    else if (blockIdx.z == 1) gemm_body(xk, Wk, bk, ok, dyn);
    else                      gemm_body(xv, Wv, bv, ov, dyn);
}

__global__ __launch_bounds__(256) void k_gemm1(
    const float* A, const float* B, const float* bias, float* Co) {
    extern __shared__ __nv_bfloat16 dyn[];
    gemm_body(A, B, bias, Co, dyn);
}

__global__ __launch_bounds__(256) void k_simE_mma() {
    extern __shared__ __nv_bfloat16 dyn[];
    const int tid = threadIdx.x, warp = tid >> 5, lane = tid & 31;
    const int g = lane >> 2, tg = lane & 3;
    const int bb = blockIdx.z, m0 = blockIdx.x * 128, n0 = blockIdx.y * 128;
    const int wm = (warp & 1) * 64, wn = (warp >> 1) * 32;
    float acc[4][4][4];
    #pragma unroll
    for (int mi = 0; mi < 4; mi++)
        #pragma unroll
        for (int ni = 0; ni < 4; ni++)
            #pragma unroll
            for (int e = 0; e < 4; e++) acc[mi][ni][e] = 0.0f;
    const int lrow = tid >> 1, half = tid & 1;
    const __nv_bfloat16* K0 = g_ks0 + (size_t)(bb*MM + m0 + lrow) * CC;
    const __nv_bfloat16* K1 = g_ks1 + (size_t)(bb*MM + m0 + lrow) * CC;
    const __nv_bfloat16* Q0 = g_qs0 + ((size_t)(n0 + lrow)*NB + bb) * CC;
    const __nv_bfloat16* Q1 = g_qs1 + ((size_t)(n0 + lrow)*NB + bb) * CC;
    #pragma unroll
    for (int u = 0; u < 2; u++) {
        int seg = half*2 + u;
        *(uint4*)&ASP(0,0,lrow,seg*8) = *(const uint4*)(K0 + seg*8);
        *(uint4*)&ASP(0,1,lrow,seg*8) = *(const uint4*)(K1 + seg*8);
        *(uint4*)&BSP(0,0,lrow,seg*8) = *(const uint4*)(Q0 + seg*8);
        *(uint4*)&BSP(0,1,lrow,seg*8) = *(const uint4*)(Q1 + seg*8);
    }
    __syncthreads();
    const int NCH = CC/32;
    for (int ci = 0; ci < NCH; ci++) {
        const int cur = ci & 1;
        uint4 rk0[2], rk1[2], rq0[2], rq1[2];
        if (ci + 1 < NCH) {
            int k0 = (ci+1)*32;
            #pragma unroll
            for (int u = 0; u < 2; u++) {
                int seg = half*2 + u;
                rk0[u] = *(const uint4*)(K0 + k0 + seg*8);
                rk1[u] = *(const uint4*)(K1 + k0 + seg*8);
                rq0[u] = *(const uint4*)(Q0 + k0 + seg*8);
                rq1[u] = *(const uint4*)(Q1 + k0 + seg*8);
            }
        }
        #pragma unroll
        for (int kk = 0; kk < 32; kk += 16) { MMA_FRAGS_P(cur) }
        if (ci + 1 < NCH) {
            int nb = cur ^ 1;
            #pragma unroll
            for (int u = 0; u < 2; u++) {
                int seg = half*2 + u;
                *(uint4*)&ASP(nb,0,lrow,seg*8) = rk0[u];
                *(uint4*)&ASP(nb,1,lrow,seg*8) = rk1[u];
                *(uint4*)&BSP(nb,0,lrow,seg*8) = rq0[u];
                *(uint4*)&BSP(nb,1,lrow,seg*8) = rq1[u];
            }
        }
        __syncthreads();
    }
    #pragma unroll
    for (int mi = 0; mi < 4; mi++) {
        int mA = m0 + wm + mi*16 + g;
        int mB = mA + 8;
        int mkA = g_maskb[bb*MM + mA], mkB = g_maskb[bb*MM + mB];
        size_t baseA = ((size_t)bb*MM + mA) * NQ;
        size_t baseB = ((size_t)bb*MM + mB) * NQ;
        #pragma unroll
        for (int ni = 0; ni < 4; ni++) {
            int c = n0 + wn + ni*8 + tg*2;
            float s0 = acc[mi][ni][0], s1 = acc[mi][ni][1];
            float s2 = acc[mi][ni][2], s3 = acc[mi][ni][3];
            g_sim[baseA + c]   = s0; g_sim[baseA + c+1] = s1;
            g_sim[baseB + c]   = s2; g_sim[baseB + c+1] = s3;
            float e0 = mkA ? expf((s0 - 1.0f) * EPS_INV) : 0.0f;
            float e1 = mkA ? expf((s1 - 1.0f) * EPS_INV) : 0.0f;
            float e2 = mkB ? expf((s2 - 1.0f) * EPS_INV) : 0.0f;
            float e3 = mkB ? expf((s3 - 1.0f) * EPS_INV) : 0.0f;
            g_E[baseA + c]   = e0; g_E[baseA + c+1] = e1;
            g_E[baseB + c]   = e2; g_E[baseB + c+1] = e3;
            g_Ebf[baseA + c]   = __float2bfloat16(e0);
            g_Ebf[baseA + c+1] = __float2bfloat16(e1);
            g_Ebf[baseB + c]   = __float2bfloat16(e2);
            g_Ebf[baseB + c+1] = __float2bfloat16(e3);
        }
    }
}

// HMMA TN xgemm (unchanged)
#define MMA_FRAGS_S \
    uint32_t af[2][4][4], bfr[2][4][2]; \
    _Pragma("unroll") \
    for (int s = 0; s < 2; s++) { \
        _Pragma("unroll") \
        for (int mi = 0; mi < 4; mi++) { \
            int r0 = wm + mi*16 + g; \
            af[s][mi][0] = *(const uint32_t*)&As[s][r0][kk + tg*2]; \
            af[s][mi][1] = *(const uint32_t*)&As[s][r0+8][kk + tg*2]; \
            af[s][mi][2] = *(const uint32_t*)&As[s][r0][kk + tg*2 + 8]; \
            af[s][mi][3] = *(const uint32_t*)&As[s][r0+8][kk + tg*2 + 8]; \
        } \
        _Pragma("unroll") \
        for (int ni = 0; ni < 4; ni++) { \
            int c0 = wn + ni*8 + g; \
            bfr[s][ni][0] = *(const uint32_t*)&Bs[s][c0][kk + tg*2]; \
            bfr[s][ni][1] = *(const uint32_t*)&Bs[s][c0][kk + tg*2 + 8]; \
        } \
    } \
    _Pragma("unroll") \
    for (int p = 0; p < 3; p++) { \
        const int sa = (p == 2) ? 1 : 0, sb = (p == 1) ? 1 : 0; \
        _Pragma("unroll") \
        for (int mi = 0; mi < 4; mi++) \
            _Pragma("unroll") \
            for (int ni = 0; ni < 4; ni++) \
                asm volatile( \
                    "mma.sync.aligned.m16n8k16.row.col.f32.bf16.bf16.f32 " \
                    "{%0,%1,%2,%3}, {%4,%5,%6,%7}, {%8,%9}, {%0,%1,%2,%3};" \
                    : "+f"(acc[mi][ni][0]), "+f"(acc[mi][ni][1]), \
                      "+f"(acc[mi][ni][2]), "+f"(acc[mi][ni][3]) \
                    : "r"(af[sa][mi][0]), "r"(af[sa][mi][1]), \
                      "r"(af[sa][mi][2]), "r"(af[sa][mi][3]), \
                      "r"(bfr[sb][ni][0]), "r"(bfr[sb][ni][1])); \
    }

__global__ __launch_bounds__(256) void k_xgemm_mma() {
    __shared__ __nv_bfloat16 As[2][128][SPAD];
    __shared__ __nv_bfloat16 Bs[2][128][SPAD];
    const int tid = threadIdx.x, warp = tid >> 5, lane = tid & 31;
    const int g = lane >> 2, tg = lane & 3;
    const int bb = blockIdx.z, n0 = blockIdx.x * 128, c0 = blockIdx.y * 128;
    const int wm = (warp & 1) * 64, wn = (warp >> 1) * 32;
    float acc[4][4][4];
    #pragma unroll
    for (int mi = 0; mi < 4; mi++)
        #pragma unroll
        for (int ni = 0; ni < 4; ni++)
            #pragma unroll
            for (int e = 0; e < 4; e++) acc[mi][ni][e] = 0.0f;
    const float* Eb = g_E + (size_t)bb*MM*NQ;
    const float* Vb = g_v + (size_t)bb*MM*CC;
    const int lm = tid & 31, lg = tid >> 5;
    for (int k0 = 0; k0 < MM; k0 += 32) {
        int m = k0 + lm;
        float am = g_a[bb*MM + m];
        #pragma unroll
        for (int j = 0; j < 4; j++) {
            int n = lg*16 + j*4;
            float4 ev = *(const float4*)(Eb + (size_t)m*NQ + n0 + n);
            float4 vv = *(const float4*)(Vb + (size_t)m*CC + c0 + n);
            vv.x *= am; vv.y *= am; vv.z *= am; vv.w *= am;
            float ee[4] = {ev.x, ev.y, ev.z, ev.w};
            float va[4] = {vv.x, vv.y, vv.z, vv.w};
            #pragma unroll
            for (int q = 0; q < 4; q++) {
                __nv_bfloat16 h = __float2bfloat16(ee[q]);
                As[0][n + q][lm] = h;
                As[1][n + q][lm] = __float2bfloat16(ee[q] - __bfloat162float(h));
                __nv_bfloat16 hv = __float2bfloat16(va[q]);
                Bs[0][n + q][lm] = hv;
                Bs[1][n + q][lm] = __float2bfloat16(va[q] - __bfloat162float(hv));
            }
        }
        __syncthreads();
        #pragma unroll
        for (int kk = 0; kk < 32; kk += 16) { MMA_FRAGS_S }
        __syncthreads();
    }
    #pragma unroll
    for (int mi = 0; mi < 4; mi++) {
        int nA = n0 + wm + mi*16 + g;
        int nB = nA + 8;
        float bnA = g_bfin[bb*NQ + nA], bnB = g_bfin[bb*NQ + nB];
        #pragma unroll
        for (int ni = 0; ni < 4; ni++) {
            int c = c0 + wn + ni*8 + tg*2;
            g_x[((size_t)nA*NB + bb)*CC + c]   = acc[mi][ni][0] * bnA;
            g_x[((size_t)nA*NB + bb)*CC + c+1] = acc[mi][ni][1] * bnA;
            g_x[((size_t)nB*NB + bb)*CC + c]   = acc[mi][ni][2] * bnB;
            g_x[((size_t)nB*NB + bb)*CC + c+1] = acc[mi][ni][3] * bnB;
        }
    }
}

// persistent Sinkhorn: smem E, atomic+nanosleep barrier (proven R12), fused attn epilogue
#define SINK_SMEM (64*NQ*2 + 8*NQ*4)
__global__ __launch_bounds__(256) void k_sink_pers(float* attn_out) {
    extern __shared__ char dsm[];
    __nv_bfloat16* Es = (__nv_bfloat16*)dsm;
    float* shred = (float*)(dsm + 64*NQ*2);
    const int blk = blockIdx.x, bb = blk >> 4, rb = blk & 15;
    const int tid = threadIdx.x, warp = tid >> 5, lane = tid & 31;
    const int col = tid * 4;
    {
        const uint4* src = (const uint4*)(g_Ebf + ((size_t)bb*MM + rb*64) * NQ);
        uint4* dst = (uint4*)Es;
        for (int i = tid; i < 64*NQ/8; i += 256) dst[i] = src[i];
    }
    __syncthreads();
    float bv[32];
    #pragma unroll
    for (int q = 0; q < 32; q++) bv[q] = 1.0f;
    float a_loc[8];
    #pragma unroll
    for (int q = 0; q < 8; q++) a_loc[q] = 0.0f;
    for (int it = 1; it <= NITER; it++) {
        float cacc[32];
        #pragma unroll
        for (int q = 0; q < 32; q++) cacc[q] = 0.0f;
        #pragma unroll
        for (int rr = 0; rr < 8; rr++) {
            int lr = warp*8 + rr;
            int m = rb*64 + lr;
            if (!g_maskb[bb*MM + m]) {
                if (it == NITER && lane == 0) g_a[bb*MM + m] = 0.0f;
                continue;
            }
            const __nv_bfloat16* er = Es + (size_t)lr * NQ;
            float e[32], s = 0.0f;
            #pragma unroll
            for (int g = 0; g < 8; g++) {
                uint2 w = *(const uint2*)(er + g*128 + lane*4);
                __nv_bfloat162 p0 = *(__nv_bfloat162*)&w.x;
                __nv_bfloat162 p1 = *(__nv_bfloat162*)&w.y;
                e[g*4+0] = __bfloat162float(__low2bfloat16(p0));
                e[g*4+1] = __bfloat162float(__high2bfloat16(p0));
                e[g*4+2] = __bfloat162float(__low2bfloat16(p1));
                e[g*4+3] = __bfloat162float(__high2bfloat16(p1));
                s += e[g*4+0]*bv[g*4+0] + e[g*4+1]*bv[g*4+1]
                   + e[g*4+2]*bv[g*4+2] + e[g*4+3]*bv[g*4+3];
            }
            #pragma unroll
            for (int o = 16; o; o >>= 1) s += __shfl_xor_sync(0xffffffffu, s, o);
            float a = g_mu[bb*MM + m] / s;
            if (it == NITER) {
                a_loc[rr] = a;
                if (lane == 0) g_a[bb*MM + m] = a;
            }
            #pragma unroll
            for (int q = 0; q < 32; q++) cacc[q] += a * e[q];
        }
        #pragma unroll
        for (int g = 0; g < 8; g++)
            *(float4*)&shred[warp*1024 + g*128 + lane*4] =
                make_float4(cacc[g*4], cacc[g*4+1], cacc[g*4+2], cacc[g*4+3]);
        __syncthreads();
        float s0=0, s1=0, s2=0, s3=0;
        #pragma unroll
        for (int w = 0; w < 8; w++) {
            float4 v = *(const float4*)&shred[w*1024 + col];
            s0 += v.x; s1 += v.y; s2 += v.z; s3 += v.w;
        }
        *(float4*)&g_cpart[(size_t)blk*NQ + col] = make_float4(s0, s1, s2, s3);
        __threadfence();
        __syncthreads();
        if (tid == 0) {
            atomicAdd(&g_bar8[bb], 1u);
            unsigned int target = (unsigned int)it * 16u;
            while (atomicAdd(&g_bar8[bb], 0u) < target) __nanosleep(64);
        }
        __syncthreads();
        __threadfence();
        if (it < NITER) {
            float c0=0, c1=0, c2=0, c3=0;
            #pragma unroll
            for (int w = 0; w < 16; w++) {
                float4 v = *(const float4*)&g_cpart[(size_t)(bb*16 + w)*NQ + col];
                c0 += v.x; c1 += v.y; c2 += v.z; c3 += v.w;
            }
            shred[col+0] = NU_P / c0; shred[col+1] = NU_P / c1;
            shred[col+2] = NU_P / c2; shred[col+3] = NU_P / c3;
            __syncthreads();
            #pragma unroll
            for (int g = 0; g < 8; g++) {
                float4 v = *(const float4*)&shred[g*128 + lane*4];
                bv[g*4+0]=v.x; bv[g*4+1]=v.y; bv[g*4+2]=v.z; bv[g*4+3]=v.w;
            }
            __syncthreads();
        }
    }
    // final b (all blocks compute into shred; rb==0 also writes g_bfin)
    {
        float c0=0, c1=0, c2=0, c3=0;
        #pragma unroll
        for (int w = 0; w < 16; w++) {
            float4 v = *(const float4*)&g_cpart[(size_t)(bb*16 + w)*NQ + col];
            c0 += v.x; c1 += v.y; c2 += v.z; c3 += v.w;
        }
        float b0 = NU_P / c0, b1 = NU_P / c1, b2 = NU_P / c2, b3 = NU_P / c3;
        shred[col+0] = b0; shred[col+1] = b1; shred[col+2] = b2; shred[col+3] = b3;
        if (rb == 0) {
            g_bfin[bb*NQ+col+0] = b0; g_bfin[bb*NQ+col+1] = b1;
            g_bfin[bb*NQ+col+2] = b2; g_bfin[bb*NQ+col+3] = b3;
        }
    }
    __syncthreads();
    // fused attn: attn[b][m] = M*Nq * a_m * sum_n sim*E*b_n (E rows in smem)
    if (attn_out) {
        #pragma unroll
        for (int rr = 0; rr < 8; rr++) {
            int lr = warp*8 + rr;
            int m = rb*64 + lr;
            float aL = a_loc[rr];
            float s = 0.0f;
            if (aL != 0.0f) {
                const float* S = g_sim + ((size_t)bb*MM + m) * NQ;
                const __nv_bfloat16* er = Es + (size_t)lr * NQ;
                #pragma unroll
                for (int g = 0; g < 8; g++) {
                    int n = g*128 + lane*4;
                    float4 sv = *(const float4*)(S + n);
                    uint2 w = *(const uint2*)(er + n);
                    __nv_bfloat162 p0 = *(__nv_bfloat162*)&w.x;
                    __nv_bfloat162 p1 = *(__nv_bfloat162*)&w.y;
                    float4 bvv = *(const float4*)&shred[n];
                    s += sv.x * __bfloat162float(__low2bfloat16(p0))  * bvv.x
                       + sv.y * __bfloat162float(__high2bfloat16(p0)) * bvv.y
                       + sv.z * __bfloat162float(__low2bfloat16(p1))  * bvv.z
                       + sv.w * __bfloat162float(__high2bfloat16(p1)) * bvv.w;
                }
                #pragma unroll
                for (int o = 16; o; o >>= 1) s += __shfl_xor_sync(0xffffffffu, s, o);
            }
            if (lane == 0) attn_out[bb*MM + m] = 1048576.0f * aL * s;
        }
    }
}

extern "C" void kernel_launch(void* const* d_in, const int* in_sizes, int n_in,
                              void* d_out, int out_size) {
    const float* xq = (const float*)d_in[0];
    const float* xk = (const float*)d_in[1];
    const float* xv = (const float*)d_in[2];
    const void*  mk = d_in[3];
    const float* Wq = (const float*)d_in[4];
    const float* bq = (const float*)d_in[5];
    const float* Wk = (const float*)d_in[6];
    const float* bk = (const float*)d_in[7];
    const float* Wv = (const float*)d_in[8];
    const float* bv = (const float*)d_in[9];
    const float* Wp = (const float*)d_in[10];
    const float* bp = (const float*)d_in[11];
    float *qp, *kp, *vp, *xp;
    __nv_bfloat16 *q0, *q1, *ks0, *ks1;
    cudaGetSymbolAddress((void**)&qp, g_q);
    cudaGetSymbolAddress((void**)&kp, g_k);
    cudaGetSymbolAddress((void**)&vp, g_v);
    cudaGetSymbolAddress((void**)&xp, g_x);
    cudaGetSymbolAddress((void**)&q0, g_qs0);
    cudaGetSymbolAddress((void**)&q1, g_qs1);
    cudaGetSymbolAddress((void**)&ks0, g_ks0);
    cudaGetSymbolAddress((void**)&ks1, g_ks1);
    cudaFuncSetAttribute(k_gemm3, cudaFuncAttributeMaxDynamicSharedMemorySize, DYN_BYTES);
    cudaFuncSetAttribute(k_gemm1, cudaFuncAttributeMaxDynamicSharedMemorySize, DYN_BYTES);
    cudaFuncSetAttribute(k_simE_mma, cudaFuncAttributeMaxDynamicSharedMemorySize, DYN_BYTES);
    cudaFuncSetAttribute(k_sink_pers, cudaFuncAttributeMaxDynamicSharedMemorySize, SINK_SMEM);

    k_detect<<<1, 256>>>((const unsigned char*)mk);
    k_counts<<<NB, 256>>>(mk);
    k_init<<<(RR + 255)/256, 256>>>(mk);

    k_gemm3<<<dim3(RR/128, CC/128, 3), 256, DYN_BYTES>>>(
        xq, Wq, bq, qp, xk, Wk, bk, kp, xv, Wv, bv, vp);

    k_l2split<<<RR, 256>>>(qp, q0, q1);
    k_l2split<<<RR, 256>>>(kp, ks0, ks1);

    k_simE_mma<<<dim3(MM/128, NQ/128, NB), 256, DYN_BYTES>>>();

    float* attn_ptr = (out_size >= RR*CC + RR) ? ((float*)d_out + (size_t)RR*CC) : nullptr;
    k_sink_pers<<<128, 256, SINK_SMEM>>>(attn_ptr);

    k_xgemm_mma<<<dim3(NQ/128, CC/128, NB), 256>>>();

    k_gemm1<<<dim3(RR/128, CC/128), 256, DYN_BYTES>>>(xp, Wp, bp, (float*)d_out);
}

// round 16
// speedup vs baseline: 1.4957x; 1.0270x over previous
#include <cuda_runtime.h>
#include <cuda_bf16.h>
#include <math.h>
#include <stdint.h>

#define NQ 1024
#define NB 8
#define MM 1024
#define CC 640
#define RR 8192
#define NITER 100
#define EPS_INV 20.0f
#define NU_P (1.0f/1024.0f + 1e-8f)

__device__ float g_q[RR*CC];
__device__ float g_k[RR*CC];
__device__ float g_v[RR*CC];
__device__ float g_x[RR*CC];
__device__ float g_sim[NB*MM*NQ];
__device__ float g_E[NB*MM*NQ];
__device__ __nv_bfloat16 g_Ebf[NB*MM*NQ];
__device__ float g_cpart[128*NQ];
__device__ float g_a[RR];
__device__ float g_mu[RR];
__device__ float g_bfin[RR];
__device__ unsigned char g_maskb[RR];
__device__ int g_counts[NB];
__device__ int g_mfmt;
__device__ unsigned int g_bar8[NB];
__device__ __nv_bfloat16 g_qs0[RR*CC];
__device__ __nv_bfloat16 g_qs1[RR*CC];
__device__ __nv_bfloat16 g_ks0[RR*CC];
__device__ __nv_bfloat16 g_ks1[RR*CC];
// pre-split bf16 inputs for cp.async GEMMs
__device__ __nv_bfloat16 g_sa0[3*RR*CC];
__device__ __nv_bfloat16 g_sa1[3*RR*CC];
__device__ __nv_bfloat16 g_sw0[3*CC*CC];
__device__ __nv_bfloat16 g_sw1[3*CC*CC];

__device__ __forceinline__ int getmask_raw(const void* m, int idx, int fmt) {
    if (fmt == 1) return ((const int*)m)[idx] != 0;
    if (fmt == 2) return ((const float*)m)[idx] != 0.0f;
    return ((const unsigned char*)m)[idx] != 0;
}

__global__ void k_detect(const unsigned char* m) {
    __shared__ int cA, cB;
    if (threadIdx.x == 0) { cA = 0; cB = 0; }
    __syncthreads();
    int a = 0, b = 0;
    for (int i = threadIdx.x; i < RR; i += blockDim.x) {
        if (m[i] != 0) { if ((i & 3) == 0) a = 1; else b = 1; }
    }
    if (a) atomicOr(&cA, 1);
    if (b) atomicOr(&cB, 1);
    __syncthreads();
    if (threadIdx.x == 0) g_mfmt = (cB == 0) ? 1 : ((cA == 0) ? 2 : 0);
}

__global__ void k_counts(const void* mask) {
    __shared__ int sh[256];
    int fmt = g_mfmt, bb = blockIdx.x, s = 0;
    for (int m = threadIdx.x; m < MM; m += 256) s += getmask_raw(mask, bb*MM + m, fmt);
    sh[threadIdx.x] = s; __syncthreads();
    for (int o = 128; o; o >>= 1) { if (threadIdx.x < o) sh[threadIdx.x] += sh[threadIdx.x + o]; __syncthreads(); }
    if (threadIdx.x == 0) g_counts[bb] = (sh[0] > 0) ? sh[0] : 1;
}

__global__ void k_init(const void* mask) {
    int idx = blockIdx.x * blockDim.x + threadIdx.x;
    if (idx < NB) g_bar8[idx] = 0u;
    if (idx < RR) {
        int fmt = g_mfmt;
        int mk = getmask_raw(mask, idx, fmt);
        g_maskb[idx] = (unsigned char)mk;
        g_mu[idx] = mk ? (1.0f/(float)g_counts[idx >> 10] + 1e-8f) : 0.0f;
    }
}

__device__ __forceinline__ void split1(float x, __nv_bfloat16* d0, __nv_bfloat16* d1, size_t i) {
    __nv_bfloat16 b0 = __float2bfloat16(x);
    d0[i] = b0; d1[i] = __float2bfloat16(x - __bfloat162float(b0));
}

// batched split: 3 activation tensors (RR*CC) then 3 weight tensors (CC*CC)
__global__ void k_splitmulti(const float* a0, const float* a1, const float* a2,
                             const float* w0, const float* w1, const float* w2) {
    const int NA = RR*CC, NW = CC*CC;
    long long idx = (long long)blockIdx.x * blockDim.x + threadIdx.x;
    long long tot = 3LL*NA + 3LL*NW;
    if (idx >= tot) return;
    if (idx < 3LL*NA) {
        int t = (int)(idx / NA), i = (int)(idx % NA);
        const float* s = (t == 0) ? a0 : (t == 1) ? a1 : a2;
        split1(s[i], g_sa0, g_sa1, (size_t)t*NA + i);
    } else {
        long long r = idx - 3LL*NA;
        int t = (int)(r / NW), i = (int)(r % NW);
        const float* s = (t == 0) ? w0 : (t == 1) ? w1 : w2;
        split1(s[i], g_sw0, g_sw1, (size_t)t*NW + i);
    }
}

__global__ void k_split2(const float* __restrict__ src,
                         __nv_bfloat16* __restrict__ d0,
                         __nv_bfloat16* __restrict__ d1, int n) {
    int i = blockIdx.x * blockDim.x + threadIdx.x;
    if (i >= n) return;
    split1(src[i], d0, d1, i);
}

__global__ void k_l2split(const float* __restrict__ src,
                          __nv_bfloat16* __restrict__ d0,
                          __nv_bfloat16* __restrict__ d1) {
    __shared__ float sh[256];
    const float* row = src + (size_t)blockIdx.x * CC;
    float s = 0.0f;
    for (int i = threadIdx.x; i < CC; i += 256) { float v = row[i]; s += v*v; }
    sh[threadIdx.x] = s; __syncthreads();
    for (int o = 128; o; o >>= 1) { if (threadIdx.x < o) sh[threadIdx.x] += sh[threadIdx.x + o]; __syncthreads(); }
    float inv = 1.0f / fmaxf(sqrtf(sh[0]), 1e-12f);
    size_t base = (size_t)blockIdx.x * CC;
    for (int i = threadIdx.x; i < CC; i += 256) {
        float x = row[i] * inv;
        split1(x, d0, d1, base + i);
    }
}

// ---- cp.async helpers ----
__device__ __forceinline__ void cpa16(void* sptr, const void* gptr) {
    uint32_t sa = (uint32_t)__cvta_generic_to_shared(sptr);
    asm volatile("cp.async.cg.shared.global [%0], [%1], 16;" :: "r"(sa), "l"(gptr));
}
#define CP_COMMIT asm volatile("cp.async.commit_group;" ::: "memory")
#define CP_WAIT0  asm volatile("cp.async.wait_group 0;" ::: "memory")

// ---- double-buffered smem layout (chunk 32) ----
#define SPAD 40
#define BOFF (4*128*SPAD)
#define ASP(b,s,r,c) dyn[(((b)*2+(s))*128 + (r))*SPAD + (c)]
#define BSP(b,s,r,c) dyn[BOFF + (((b)*2+(s))*128 + (r))*SPAD + (c)]
#define DYN_BYTES (2*BOFF*2)

#define MMA_FRAGS_P(B) \
    uint32_t af[2][4][4], bfr[2][4][2]; \
    _Pragma("unroll") \
    for (int s = 0; s < 2; s++) { \
        _Pragma("unroll") \
        for (int mi = 0; mi < 4; mi++) { \
            int r0 = wm + mi*16 + g; \
            af[s][mi][0] = *(const uint32_t*)&ASP(B, s, r0,   kk + tg*2); \
            af[s][mi][1] = *(const uint32_t*)&ASP(B, s, r0+8, kk + tg*2); \
            af[s][mi][2] = *(const uint32_t*)&ASP(B, s, r0,   kk + tg*2 + 8); \
            af[s][mi][3] = *(const uint32_t*)&ASP(B, s, r0+8, kk + tg*2 + 8); \
        } \
        _Pragma("unroll") \
        for (int ni = 0; ni < 4; ni++) { \
            int c0 = wn + ni*8 + g; \
            bfr[s][ni][0] = *(const uint32_t*)&BSP(B, s, c0, kk + tg*2); \
            bfr[s][ni][1] = *(const uint32_t*)&BSP(B, s, c0, kk + tg*2 + 8); \
        } \
    } \
    _Pragma("unroll") \
    for (int p = 0; p < 3; p++) { \
        const int sa = (p == 2) ? 1 : 0, sb = (p == 1) ? 1 : 0; \
        _Pragma("unroll") \
        for (int mi = 0; mi < 4; mi++) \
            _Pragma("unroll") \
            for (int ni = 0; ni < 4; ni++) \
                asm volatile( \
                    "mma.sync.aligned.m16n8k16.row.col.f32.bf16.bf16.f32 " \
                    "{%0,%1,%2,%3}, {%4,%5,%6,%7}, {%8,%9}, {%0,%1,%2,%3};" \
                    : "+f"(acc[mi][ni][0]), "+f"(acc[mi][ni][1]), \
                      "+f"(acc[mi][ni][2]), "+f"(acc[mi][ni][3]) \
                    : "r"(af[sa][mi][0]), "r"(af[sa][mi][1]), \
                      "r"(af[sa][mi][2]), "r"(af[sa][mi][3]), \
                      "r"(bfr[sb][ni][0]), "r"(bfr[sb][ni][1])); \
    }

// issue one chunk's cp.async copies (bf16 A/B hi+lo) into buffer b
#define CP_ISSUE(b, k0) \
    _Pragma("unroll") \
    for (int u = 0; u < 2; u++) { \
        int seg = half*2 + u; \
        cpa16(&ASP(b,0,lrow,seg*8), Ab0 + (k0) + seg*8); \
        cpa16(&ASP(b,1,lrow,seg*8), Ab1 + (k0) + seg*8); \
        cpa16(&BSP(b,0,lrow,seg*8), Bb0 + (k0) + seg*8); \
        cpa16(&BSP(b,1,lrow,seg*8), Bb1 + (k0) + seg*8); \
    } \
    CP_COMMIT;

// cp.async NT GEMM body (bf16 pre-split inputs): C = A*B^T + bias
__device__ __forceinline__ void gemm_body_ca(
    const __nv_bfloat16* __restrict__ A0, const __nv_bfloat16* __restrict__ A1,
    const __nv_bfloat16* __restrict__ B0, const __nv_bfloat16* __restrict__ B1,
    const float* __restrict__ bias, float* __restrict__ Co, __nv_bfloat16* dyn) {
    const int tid = threadIdx.x, warp = tid >> 5, lane = tid & 31;
    const int g = lane >> 2, tg = lane & 3;
    const int i0 = blockIdx.x * 128, j0 = blockIdx.y * 128;
    const int wm = (warp & 1) * 64, wn = (warp >> 1) * 32;
    float acc[4][4][4];
    #pragma unroll
    for (int mi = 0; mi < 4; mi++)
        #pragma unroll
        for (int ni = 0; ni < 4; ni++)
            #pragma unroll
            for (int e = 0; e < 4; e++) acc[mi][ni][e] = 0.0f;
    const int lrow = tid >> 1, half = tid & 1;
    const __nv_bfloat16* Ab0 = A0 + (size_t)(i0 + lrow) * CC;
    const __nv_bfloat16* Ab1 = A1 + (size_t)(i0 + lrow) * CC;
    const __nv_bfloat16* Bb0 = B0 + (size_t)(j0 + lrow) * CC;
    const __nv_bfloat16* Bb1 = B1 + (size_t)(j0 + lrow) * CC;
    CP_ISSUE(0, 0)
    CP_WAIT0; __syncthreads();
    const int NCH = CC/32;
    for (int ci = 0; ci < NCH; ci++) {
        const int cur = ci & 1;
        if (ci + 1 < NCH) { CP_ISSUE(cur ^ 1, (ci+1)*32) }
        #pragma unroll
        for (int kk = 0; kk < 32; kk += 16) { MMA_FRAGS_P(cur) }
        CP_WAIT0; __syncthreads();
    }
    #pragma unroll
    for (int mi = 0; mi < 4; mi++) {
        int r0 = i0 + wm + mi*16 + g;
        #pragma unroll
        for (int ni = 0; ni < 4; ni++) {
            int c = j0 + wn + ni*8 + tg*2;
            float b0v = bias[c], b1v = bias[c+1];
            Co[(size_t)r0*CC + c]       = acc[mi][ni][0] + b0v;
            Co[(size_t)r0*CC + c+1]     = acc[mi][ni][1] + b1v;
            Co[(size_t)(r0+8)*CC + c]   = acc[mi][ni][2] + b0v;
            Co[(size_t)(r0+8)*CC + c+1] = acc[mi][ni][3] + b1v;
        }
    }
}

__global__ __launch_bounds__(256, 2) void k_gemm3(
    const float* bq, float* oq, const float* bk, float* ok,
    const float* bv, float* ov) {
    extern __shared__ __nv_bfloat16 dyn[];
    const int z = blockIdx.z;
    const __nv_bfloat16* A0 = g_sa0 + (size_t)z*RR*CC;
    const __nv_bfloat16* A1 = g_sa1 + (size_t)z*RR*CC;
    const __nv_bfloat16* B0 = g_sw0 + (size_t)z*CC*CC;
    const __nv_bfloat16* B1 = g_sw1 + (size_t)z*CC*CC;
    if (z == 0)      gemm_body_ca(A0, A1, B0, B1, bq, oq, dyn);
    else if (z == 1) gemm_body_ca(A0, A1, B0, B1, bk, ok, dyn);
    else             gemm_body_ca(A0, A1, B0, B1, bv, ov, dyn);
}

__global__ __launch_bounds__(256, 2) void k_gemm1(const float* bias, float* Co) {
    extern __shared__ __nv_bfloat16 dyn[];
    gemm_body_ca(g_sa0, g_sa1, g_sw0, g_sw1, bias, Co, dyn);
}

// cp.async simE (bf16 q/k splits)
__global__ __launch_bounds__(256, 2) void k_simE_mma() {
    extern __shared__ __nv_bfloat16 dyn[];
    const int tid = threadIdx.x, warp = tid >> 5, lane = tid & 31;
    const int g = lane >> 2, tg = lane & 3;
    const int bb = blockIdx.z, m0 = blockIdx.x * 128, n0 = blockIdx.y * 128;
    const int wm = (warp & 1) * 64, wn = (warp >> 1) * 32;
    float acc[4][4][4];
    #pragma unroll
    for (int mi = 0; mi < 4; mi++)
        #pragma unroll
        for (int ni = 0; ni < 4; ni++)
            #pragma unroll
            for (int e = 0; e < 4; e++) acc[mi][ni][e] = 0.0f;
    const int lrow = tid >> 1, half = tid & 1;
    const __nv_bfloat16* Ab0 = g_ks0 + (size_t)(bb*MM + m0 + lrow) * CC;
    const __nv_bfloat16* Ab1 = g_ks1 + (size_t)(bb*MM + m0 + lrow) * CC;
    const __nv_bfloat16* Bb0 = g_qs0 + ((size_t)(n0 + lrow)*NB + bb) * CC;
    const __nv_bfloat16* Bb1 = g_qs1 + ((size_t)(n0 + lrow)*NB + bb) * CC;
    CP_ISSUE(0, 0)
    CP_WAIT0; __syncthreads();
    const int NCH = CC/32;
    for (int ci = 0; ci < NCH; ci++) {
        const int cur = ci & 1;
        if (ci + 1 < NCH) { CP_ISSUE(cur ^ 1, (ci+1)*32) }
        #pragma unroll
        for (int kk = 0; kk < 32; kk += 16) { MMA_FRAGS_P(cur) }
        CP_WAIT0; __syncthreads();
    }
    #pragma unroll
    for (int mi = 0; mi < 4; mi++) {
        int mA = m0 + wm + mi*16 + g;
        int mB = mA + 8;
        int mkA = g_maskb[bb*MM + mA], mkB = g_maskb[bb*MM + mB];
        size_t baseA = ((size_t)bb*MM + mA) * NQ;
        size_t baseB = ((size_t)bb*MM + mB) * NQ;
        #pragma unroll
        for (int ni = 0; ni < 4; ni++) {
            int c = n0 + wn + ni*8 + tg*2;
            float s0 = acc[mi][ni][0], s1 = acc[mi][ni][1];
            float s2 = acc[mi][ni][2], s3 = acc[mi][ni][3];
            g_sim[baseA + c]   = s0; g_sim[baseA + c+1] = s1;
            g_sim[baseB + c]   = s2; g_sim[baseB + c+1] = s3;
            float e0 = mkA ? expf((s0 - 1.0f) * EPS_INV) : 0.0f;
            float e1 = mkA ? expf((s1 - 1.0f) * EPS_INV) : 0.0f;
            float e2 = mkB ? expf((s2 - 1.0f) * EPS_INV) : 0.0f;
            float e3 = mkB ? expf((s3 - 1.0f) * EPS_INV) : 0.0f;
            g_E[baseA + c]   = e0; g_E[baseA + c+1] = e1;
            g_E[baseB + c]   = e2; g_E[baseB + c+1] = e3;
            g_Ebf[baseA + c]   = __float2bfloat16(e0);
            g_Ebf[baseA + c+1] = __float2bfloat16(e1);
            g_Ebf[baseB + c]   = __float2bfloat16(e2);
            g_Ebf[baseB + c+1] = __float2bfloat16(e3);
        }
    }
}

// HMMA TN xgemm (unchanged, static smem)
#define MMA_FRAGS_S \
    uint32_t af[2][4][4], bfr[2][4][2]; \
    _Pragma("unroll") \
    for (int s = 0; s < 2; s++) { \
        _Pragma("unroll") \
        for (int mi = 0; mi < 4; mi++) { \
            int r0 = wm + mi*16 + g; \
            af[s][mi][0] = *(const uint32_t*)&As[s][r0][kk + tg*2]; \
            af[s][mi][1] = *(const uint32_t*)&As[s][r0+8][kk + tg*2]; \
            af[s][mi][2] = *(const uint32_t*)&As[s][r0][kk + tg*2 + 8]; \
            af[s][mi][3] = *(const uint32_t*)&As[s][r0+8][kk + tg*2 + 8]; \
        } \
        _Pragma("unroll") \
        for (int ni = 0; ni < 4; ni++) { \
            int c0 = wn + ni*8 + g; \
            bfr[s][ni][0] = *(const uint32_t*)&Bs[s][c0][kk + tg*2]; \
            bfr[s][ni][1] = *(const uint32_t*)&Bs[s][c0][kk + tg*2 + 8]; \
        } \
    } \
    _Pragma("unroll") \
    for (int p = 0; p < 3; p++) { \
        const int sa = (p == 2) ? 1 : 0, sb = (p == 1) ? 1 : 0; \
        _Pragma("unroll") \
        for (int mi = 0; mi < 4; mi++) \
            _Pragma("unroll") \
            for (int ni = 0; ni < 4; ni++) \
                asm volatile( \
                    "mma.sync.aligned.m16n8k16.row.col.f32.bf16.bf16.f32 " \
                    "{%0,%1,%2,%3}, {%4,%5,%6,%7}, {%8,%9}, {%0,%1,%2,%3};" \
                    : "+f"(acc[mi][ni][0]), "+f"(acc[mi][ni][1]), \
                      "+f"(acc[mi][ni][2]), "+f"(acc[mi][ni][3]) \
                    : "r"(af[sa][mi][0]), "r"(af[sa][mi][1]), \
                      "r"(af[sa][mi][2]), "r"(af[sa][mi][3]), \
                      "r"(bfr[sb][ni][0]), "r"(bfr[sb][ni][1])); \
    }

__global__ __launch_bounds__(256) void k_xgemm_mma() {
    __shared__ __nv_bfloat16 As[2][128][SPAD];
    __shared__ __nv_bfloat16 Bs[2][128][SPAD];
    const int tid = threadIdx.x, warp = tid >> 5, lane = tid & 31;
    const int g = lane >> 2, tg = lane & 3;
    const int bb = blockIdx.z, n0 = blockIdx.x * 128, c0 = blockIdx.y * 128;
    const int wm = (warp & 1) * 64, wn = (warp >> 1) * 32;
    float acc[4][4][4];
    #pragma unroll
    for (int mi = 0; mi < 4; mi++)
        #pragma unroll
        for (int ni = 0; ni < 4; ni++)
            #pragma unroll
            for (int e = 0; e < 4; e++) acc[mi][ni][e] = 0.0f;
    const float* Eb = g_E + (size_t)bb*MM*NQ;
    const float* Vb = g_v + (size_t)bb*MM*CC;
    const int lm = tid & 31, lg = tid >> 5;
    for (int k0 = 0; k0 < MM; k0 += 32) {
        int m = k0 + lm;
        float am = g_a[bb*MM + m];
        #pragma unroll
        for (int j = 0; j < 4; j++) {
            int n = lg*16 + j*4;
            float4 ev = *(const float4*)(Eb + (size_t)m*NQ + n0 + n);
            float4 vv = *(const float4*)(Vb + (size_t)m*CC + c0 + n);
            vv.x *= am; vv.y *= am; vv.z *= am; vv.w *= am;
            float ee[4] = {ev.x, ev.y, ev.z, ev.w};
            float va[4] = {vv.x, vv.y, vv.z, vv.w};
            #pragma unroll
            for (int q = 0; q < 4; q++) {
                __nv_bfloat16 h = __float2bfloat16(ee[q]);
                As[0][n + q][lm] = h;
                As[1][n + q][lm] = __float2bfloat16(ee[q] - __bfloat162float(h));
                __nv_bfloat16 hv = __float2bfloat16(va[q]);
                Bs[0][n + q][lm] = hv;
                Bs[1][n + q][lm] = __float2bfloat16(va[q] - __bfloat162float(hv));
            }
        }
        __syncthreads();
        #pragma unroll
        for (int kk = 0; kk < 32; kk += 16) { MMA_FRAGS_S }
        __syncthreads();
    }
    #pragma unroll
    for (int mi = 0; mi < 4; mi++) {
        int nA = n0 + wm + mi*16 + g;
        int nB = nA + 8;
        float bnA = g_bfin[bb*NQ + nA], bnB = g_bfin[bb*NQ + nB];
        #pragma unroll
        for (int ni = 0; ni < 4; ni++) {
            int c = c0 + wn + ni*8 + tg*2;
            g_x[((size_t)nA*NB + bb)*CC + c]   = acc[mi][ni][0] * bnA;
            g_x[((size_t)nA*NB + bb)*CC + c+1] = acc[mi][ni][1] * bnA;
            g_x[((size_t)nB*NB + bb)*CC + c]   = acc[mi][ni][2] * bnB;
            g_x[((size_t)nB*NB + bb)*CC + c+1] = acc[mi][ni][3] * bnB;
        }
    }
}

// persistent Sinkhorn: smem E, atomic+nanosleep barrier, fused attn epilogue (unchanged)
#define SINK_SMEM (64*NQ*2 + 8*NQ*4)
__global__ __launch_bounds__(256) void k_sink_pers(float* attn_out) {
    extern __shared__ char dsm[];
    __nv_bfloat16* Es = (__nv_bfloat16*)dsm;
    float* shred = (float*)(dsm + 64*NQ*2);
    const int blk = blockIdx.x, bb = blk >> 4, rb = blk & 15;
    const int tid = threadIdx.x, warp = tid >> 5, lane = tid & 31;
    const int col = tid * 4;
    {
        const uint4* src = (const uint4*)(g_Ebf + ((size_t)bb*MM + rb*64) * NQ);
        uint4* dst = (uint4*)Es;
        for (int i = tid; i < 64*NQ/8; i += 256) dst[i] = src[i];
    }
    __syncthreads();
    float bv[32];
    #pragma unroll
    for (int q = 0; q < 32; q++) bv[q] = 1.0f;
    float a_loc[8];
    #pragma unroll
    for (int q = 0; q < 8; q++) a_loc[q] = 0.0f;
    for (int it = 1; it <= NITER; it++) {
        float cacc[32];
        #pragma unroll
        for (int q = 0; q < 32; q++) cacc[q] = 0.0f;
        #pragma unroll
        for (int rr = 0; rr < 8; rr++) {
            int lr = warp*8 + rr;
            int m = rb*64 + lr;
            if (!g_maskb[bb*MM + m]) {
                if (it == NITER && lane == 0) g_a[bb*MM + m] = 0.0f;
                continue;
            }
            const __nv_bfloat16* er = Es + (size_t)lr * NQ;
            float e[32], s = 0.0f;
            #pragma unroll
            for (int g = 0; g < 8; g++) {
                uint2 w = *(const uint2*)(er + g*128 + lane*4);
                __nv_bfloat162 p0 = *(__nv_bfloat162*)&w.x;
                __nv_bfloat162 p1 = *(__nv_bfloat162*)&w.y;
                e[g*4+0] = __bfloat162float(__low2bfloat16(p0));
                e[g*4+1] = __bfloat162float(__high2bfloat16(p0));
                e[g*4+2] = __bfloat162float(__low2bfloat16(p1));
                e[g*4+3] = __bfloat162float(__high2bfloat16(p1));
                s += e[g*4+0]*bv[g*4+0] + e[g*4+1]*bv[g*4+1]
                   + e[g*4+2]*bv[g*4+2] + e[g*4+3]*bv[g*4+3];
            }
            #pragma unroll
            for (int o = 16; o; o >>= 1) s += __shfl_xor_sync(0xffffffffu, s, o);
            float a = g_mu[bb*MM + m] / s;
            if (it == NITER) {
                a_loc[rr] = a;
                if (lane == 0) g_a[bb*MM + m] = a;
            }
            #pragma unroll
            for (int q = 0; q < 32; q++) cacc[q] += a * e[q];
        }
        #pragma unroll
        for (int g = 0; g < 8; g++)
            *(float4*)&shred[warp*1024 + g*128 + lane*4] =
                make_float4(cacc[g*4], cacc[g*4+1], cacc[g*4+2], cacc[g*4+3]);
        __syncthreads();
        float s0=0, s1=0, s2=0, s3=0;
        #pragma unroll
        for (int w = 0; w < 8; w++) {
            float4 v = *(const float4*)&shred[w*1024 + col];
            s0 += v.x; s1 += v.y; s2 += v.z; s3 += v.w;
        }
        *(float4*)&g_cpart[(size_t)blk*NQ + col] = make_float4(s0, s1, s2, s3);
        __threadfence();
        __syncthreads();
        if (tid == 0) {
            atomicAdd(&g_bar8[bb], 1u);
            unsigned int target = (unsigned int)it * 16u;
            while (atomicAdd(&g_bar8[bb], 0u) < target) __nanosleep(64);
        }
        __syncthreads();
        __threadfence();
        if (it < NITER) {
            float c0=0, c1=0, c2=0, c3=0;
            #pragma unroll
            for (int w = 0; w < 16; w++) {
                float4 v = *(const float4*)&g_cpart[(size_t)(bb*16 + w)*NQ + col];
                c0 += v.x; c1 += v.y; c2 += v.z; c3 += v.w;
            }
            shred[col+0] = NU_P / c0; shred[col+1] = NU_P / c1;
            shred[col+2] = NU_P / c2; shred[col+3] = NU_P / c3;
            __syncthreads();
            #pragma unroll
            for (int g = 0; g < 8; g++) {
                float4 v = *(const float4*)&shred[g*128 + lane*4];
                bv[g*4+0]=v.x; bv[g*4+1]=v.y; bv[g*4+2]=v.z; bv[g*4+3]=v.w;
            }
            __syncthreads();
        }
    }
    {
        float c0=0, c1=0, c2=0, c3=0;
        #pragma unroll
        for (int w = 0; w < 16; w++) {
            float4 v = *(const float4*)&g_cpart[(size_t)(bb*16 + w)*NQ + col];
            c0 += v.x; c1 += v.y; c2 += v.z; c3 += v.w;
        }
        float b0 = NU_P / c0, b1 = NU_P / c1, b2 = NU_P / c2, b3 = NU_P / c3;
        shred[col+0] = b0; shred[col+1] = b1; shred[col+2] = b2; shred[col+3] = b3;
        if (rb == 0) {
            g_bfin[bb*NQ+col+0] = b0; g_bfin[bb*NQ+col+1] = b1;
            g_bfin[bb*NQ+col+2] = b2; g_bfin[bb*NQ+col+3] = b3;
        }
    }
    __syncthreads();
    if (attn_out) {
        #pragma unroll
        for (int rr = 0; rr < 8; rr++) {
            int lr = warp*8 + rr;
            int m = rb*64 + lr;
            float aL = a_loc[rr];
            float s = 0.0f;
            if (aL != 0.0f) {
                const float* S = g_sim + ((size_t)bb*MM + m) * NQ;
                const __nv_bfloat16* er = Es + (size_t)lr * NQ;
                #pragma unroll
                for (int g = 0; g < 8; g++) {
                    int n = g*128 + lane*4;
                    float4 sv = *(const float4*)(S + n);
                    uint2 w = *(const uint2*)(er + n);
                    __nv_bfloat162 p0 = *(__nv_bfloat162*)&w.x;
                    __nv_bfloat162 p1 = *(__nv_bfloat162*)&w.y;
                    float4 bvv = *(const float4*)&shred[n];
                    s += sv.x * __bfloat162float(__low2bfloat16(p0))  * bvv.x
                       + sv.y * __bfloat162float(__high2bfloat16(p0)) * bvv.y
                       + sv.z * __bfloat162float(__low2bfloat16(p1))  * bvv.z
                       + sv.w * __bfloat162float(__high2bfloat16(p1)) * bvv.w;
                }
                #pragma unroll
                for (int o = 16; o; o >>= 1) s += __shfl_xor_sync(0xffffffffu, s, o);
            }
            if (lane == 0) attn_out[bb*MM + m] = 1048576.0f * aL * s;
        }
    }
}

extern "C" void kernel_launch(void* const* d_in, const int* in_sizes, int n_in,
                              void* d_out, int out_size) {
    const float* xq = (const float*)d_in[0];
    const float* xk = (const float*)d_in[1];
    const float* xv = (const float*)d_in[2];
    const void*  mk = d_in[3];
    const float* Wq = (const float*)d_in[4];
    const float* bq = (const float*)d_in[5];
    const float* Wk = (const float*)d_in[6];
    const float* bk = (const float*)d_in[7];
    const float* Wv = (const float*)d_in[8];
    const float* bv = (const float*)d_in[9];
    const float* Wp = (const float*)d_in[10];
    const float* bp = (const float*)d_in[11];
    float *qp, *kp, *vp, *xp;
    __nv_bfloat16 *q0, *q1, *ks0, *ks1, *sa0, *sa1, *sw0, *sw1;
    cudaGetSymbolAddress((void**)&qp, g_q);
    cudaGetSymbolAddress((void**)&kp, g_k);
    cudaGetSymbolAddress((void**)&vp, g_v);
    cudaGetSymbolAddress((void**)&xp, g_x);
    cudaGetSymbolAddress((void**)&q0, g_qs0);
    cudaGetSymbolAddress((void**)&q1, g_qs1);
    cudaGetSymbolAddress((void**)&ks0, g_ks0);
    cudaGetSymbolAddress((void**)&ks1, g_ks1);
    cudaGetSymbolAddress((void**)&sa0, g_sa0);
    cudaGetSymbolAddress((void**)&sa1, g_sa1);
    cudaGetSymbolAddress((void**)&sw0, g_sw0);
    cudaGetSymbolAddress((void**)&sw1, g_sw1);
    cudaFuncSetAttribute(k_gemm3, cudaFuncAttributeMaxDynamicSharedMemorySize, DYN_BYTES);
    cudaFuncSetAttribute(k_gemm1, cudaFuncAttributeMaxDynamicSharedMemorySize, DYN_BYTES);
    cudaFuncSetAttribute(k_simE_mma, cudaFuncAttributeMaxDynamicSharedMemorySize, DYN_BYTES);
    cudaFuncSetAttribute(k_sink_pers, cudaFuncAttributeMaxDynamicSharedMemorySize, SINK_SMEM);

    k_detect<<<1, 256>>>((const unsigned char*)mk);
    k_counts<<<NB, 256>>>(mk);
    k_init<<<(RR + 255)/256, 256>>>(mk);

    {
        long long tot = 3LL*RR*CC + 3LL*CC*CC;
        k_splitmulti<<<(int)((tot + 255)/256), 256>>>(xq, xk, xv, Wq, Wk, Wv);
    }
    k_gemm3<<<dim3(RR/128, CC/128, 3), 256, DYN_BYTES>>>(bq, qp, bk, kp, bv, vp);

    k_l2split<<<RR, 256>>>(qp, q0, q1);
    k_l2split<<<RR, 256>>>(kp, ks0, ks1);

    k_simE_mma<<<dim3(MM/128, NQ/128, NB), 256, DYN_BYTES>>>();

    float* attn_ptr = (out_size >= RR*CC + RR) ? ((float*)d_out + (size_t)RR*CC) : nullptr;
    k_sink_pers<<<128, 256, SINK_SMEM>>>(attn_ptr);

    k_xgemm_mma<<<dim3(NQ/128, CC/128, NB), 256>>>();

    k_split2<<<(RR*CC + 255)/256, 256>>>(xp, sa0, sa1, RR*CC);
    k_split2<<<(CC*CC + 255)/256, 256>>>(Wp, sw0, sw1, CC*CC);
    k_gemm1<<<dim3(RR/128, CC/128), 256, DYN_BYTES>>>(bp, (float*)d_out);
}

// round 17
// speedup vs baseline: 1.5759x; 1.0536x over previous
#include <cuda_runtime.h>
#include <cuda_bf16.h>
#include <math.h>
#include <stdint.h>

#define NQ 1024
#define NB 8
#define MM 1024
#define CC 640
#define RR 8192
#define NITER 100
#define EPS_INV 20.0f
#define NU_P (1.0f/1024.0f + 1e-8f)

__device__ float g_q[RR*CC];
__device__ float g_k[RR*CC];
__device__ float g_v[RR*CC];
__device__ float g_x[RR*CC];
__device__ float g_sim[NB*MM*NQ];
__device__ float g_E[NB*MM*NQ];
__device__ __nv_bfloat16 g_Ebf[NB*MM*NQ];
__device__ float g_cpart[128*NQ];
__device__ float g_a[RR];
__device__ float g_mu[RR];
__device__ float g_bfin[RR];
__device__ unsigned char g_maskb[RR];
__device__ int g_counts[NB];
__device__ int g_mfmt;
__device__ unsigned int g_bar8[NB];
__device__ __nv_bfloat16 g_qs0[RR*CC];
__device__ __nv_bfloat16 g_qs1[RR*CC];
__device__ __nv_bfloat16 g_ks0[RR*CC];
__device__ __nv_bfloat16 g_ks1[RR*CC];
__device__ __nv_bfloat16 g_sa0[3*RR*CC];
__device__ __nv_bfloat16 g_sa1[3*RR*CC];
__device__ __nv_bfloat16 g_sw0[3*CC*CC];
__device__ __nv_bfloat16 g_sw1[3*CC*CC];

__device__ __forceinline__ int getmask_raw(const void* m, int idx, int fmt) {
    if (fmt == 1) return ((const int*)m)[idx] != 0;
    if (fmt == 2) return ((const float*)m)[idx] != 0.0f;
    return ((const unsigned char*)m)[idx] != 0;
}

__global__ void k_detect(const unsigned char* m) {
    __shared__ int cA, cB;
    if (threadIdx.x == 0) { cA = 0; cB = 0; }
    __syncthreads();
    int a = 0, b = 0;
    for (int i = threadIdx.x; i < RR; i += blockDim.x) {
        if (m[i] != 0) { if ((i & 3) == 0) a = 1; else b = 1; }
    }
    if (a) atomicOr(&cA, 1);
    if (b) atomicOr(&cB, 1);
    __syncthreads();
    if (threadIdx.x == 0) g_mfmt = (cB == 0) ? 1 : ((cA == 0) ? 2 : 0);
}

__global__ void k_counts(const void* mask) {
    __shared__ int sh[256];
    int fmt = g_mfmt, bb = blockIdx.x, s = 0;
    for (int m = threadIdx.x; m < MM; m += 256) s += getmask_raw(mask, bb*MM + m, fmt);
    sh[threadIdx.x] = s; __syncthreads();
    for (int o = 128; o; o >>= 1) { if (threadIdx.x < o) sh[threadIdx.x] += sh[threadIdx.x + o]; __syncthreads(); }
    if (threadIdx.x == 0) g_counts[bb] = (sh[0] > 0) ? sh[0] : 1;
}

__global__ void k_init(const void* mask) {
    int idx = blockIdx.x * blockDim.x + threadIdx.x;
    if (idx < NB) g_bar8[idx] = 0u;
    if (idx < RR) {
        int fmt = g_mfmt;
        int mk = getmask_raw(mask, idx, fmt);
        g_maskb[idx] = (unsigned char)mk;
        g_mu[idx] = mk ? (1.0f/(float)g_counts[idx >> 10] + 1e-8f) : 0.0f;
    }
}

__device__ __forceinline__ void split1(float x, __nv_bfloat16* d0, __nv_bfloat16* d1, size_t i) {
    __nv_bfloat16 b0 = __float2bfloat16(x);
    d0[i] = b0; d1[i] = __float2bfloat16(x - __bfloat162float(b0));
}

// float4-vectorized split of 4 consecutive elements
__device__ __forceinline__ void split4(float4 v, __nv_bfloat16* d0, __nv_bfloat16* d1, size_t i4) {
    float f[4] = {v.x, v.y, v.z, v.w};
    uint32_t hw[2], lw[2];
    #pragma unroll
    for (int j = 0; j < 2; j++) {
        __nv_bfloat16 h0 = __float2bfloat16(f[2*j]);
        __nv_bfloat16 h1 = __float2bfloat16(f[2*j+1]);
        __nv_bfloat162 hp = __halves2bfloat162(h0, h1);
        hw[j] = *(uint32_t*)&hp;
        __nv_bfloat16 l0 = __float2bfloat16(f[2*j]   - __bfloat162float(h0));
        __nv_bfloat16 l1 = __float2bfloat16(f[2*j+1] - __bfloat162float(h1));
        __nv_bfloat162 lp = __halves2bfloat162(l0, l1);
        lw[j] = *(uint32_t*)&lp;
    }
    *(uint2*)(d0 + i4*4) = make_uint2(hw[0], hw[1]);
    *(uint2*)(d1 + i4*4) = make_uint2(lw[0], lw[1]);
}

// batched vectorized split: 3 activations then 3 weights, 4 elems/thread
__global__ void k_splitmulti(const float* a0, const float* a1, const float* a2,
                             const float* w0, const float* w1, const float* w2) {
    const int NA4 = RR*CC/4, NW4 = CC*CC/4;
    long long idx = (long long)blockIdx.x * blockDim.x + threadIdx.x;
    long long tot = 3LL*NA4 + 3LL*NW4;
    if (idx >= tot) return;
    if (idx < 3LL*NA4) {
        int t = (int)(idx / NA4), i = (int)(idx % NA4);
        const float* s = (t == 0) ? a0 : (t == 1) ? a1 : a2;
        split4(*(const float4*)(s + i*4), g_sa0, g_sa1, (size_t)t*NA4 + i);
    } else {
        long long r = idx - 3LL*NA4;
        int t = (int)(r / NW4), i = (int)(r % NW4);
        const float* s = (t == 0) ? w0 : (t == 1) ? w1 : w2;
        split4(*(const float4*)(s + i*4), g_sw0, g_sw1, (size_t)t*NW4 + i);
    }
}

__global__ void k_split2v(const float* __restrict__ src,
                          __nv_bfloat16* __restrict__ d0,
                          __nv_bfloat16* __restrict__ d1, int n4) {
    int i = blockIdx.x * blockDim.x + threadIdx.x;
    if (i >= n4) return;
    split4(*(const float4*)(src + i*4), d0, d1, i);
}

__global__ void k_l2split(const float* __restrict__ src,
                          __nv_bfloat16* __restrict__ d0,
                          __nv_bfloat16* __restrict__ d1) {
    __shared__ float sh[256];
    const float* row = src + (size_t)blockIdx.x * CC;
    float s = 0.0f;
    for (int i = threadIdx.x; i < CC; i += 256) { float v = row[i]; s += v*v; }
    sh[threadIdx.x] = s; __syncthreads();
    for (int o = 128; o; o >>= 1) { if (threadIdx.x < o) sh[threadIdx.x] += sh[threadIdx.x + o]; __syncthreads(); }
    float inv = 1.0f / fmaxf(sqrtf(sh[0]), 1e-12f);
    size_t base = (size_t)blockIdx.x * CC;
    for (int i = threadIdx.x; i < CC; i += 256) {
        float x = row[i] * inv;
        split1(x, d0, d1, base + i);
    }
}

// ---- cp.async helpers ----
__device__ __forceinline__ void cpa16(void* sptr, const void* gptr) {
    uint32_t sa = (uint32_t)__cvta_generic_to_shared(sptr);
    asm volatile("cp.async.cg.shared.global [%0], [%1], 16;" :: "r"(sa), "l"(gptr));
}
#define CP_COMMIT asm volatile("cp.async.commit_group;" ::: "memory")
#define CP_WAIT0  asm volatile("cp.async.wait_group 0;" ::: "memory")

// ---- double-buffered smem layout (chunk 32) ----
#define SPAD 40
#define BOFF (4*128*SPAD)
#define ASP(b,s,r,c) dyn[(((b)*2+(s))*128 + (r))*SPAD + (c)]
#define BSP(b,s,r,c) dyn[BOFF + (((b)*2+(s))*128 + (r))*SPAD + (c)]
#define DYN_BYTES (2*BOFF*2)

#define MMA_FRAGS_P(B) \
    uint32_t af[2][4][4], bfr[2][4][2]; \
    _Pragma("unroll") \
    for (int s = 0; s < 2; s++) { \
        _Pragma("unroll") \
        for (int mi = 0; mi < 4; mi++) { \
            int r0 = wm + mi*16 + g; \
            af[s][mi][0] = *(const uint32_t*)&ASP(B, s, r0,   kk + tg*2); \
            af[s][mi][1] = *(const uint32_t*)&ASP(B, s, r0+8, kk + tg*2); \
            af[s][mi][2] = *(const uint32_t*)&ASP(B, s, r0,   kk + tg*2 + 8); \
            af[s][mi][3] = *(const uint32_t*)&ASP(B, s, r0+8, kk + tg*2 + 8); \
        } \
        _Pragma("unroll") \
        for (int ni = 0; ni < 4; ni++) { \
            int c0 = wn + ni*8 + g; \
            bfr[s][ni][0] = *(const uint32_t*)&BSP(B, s, c0, kk + tg*2); \
            bfr[s][ni][1] = *(const uint32_t*)&BSP(B, s, c0, kk + tg*2 + 8); \
        } \
    } \
    _Pragma("unroll") \
    for (int p = 0; p < 3; p++) { \
        const int sa = (p == 2) ? 1 : 0, sb = (p == 1) ? 1 : 0; \
        _Pragma("unroll") \
        for (int mi = 0; mi < 4; mi++) \
            _Pragma("unroll") \
            for (int ni = 0; ni < 4; ni++) \
                asm volatile( \
                    "mma.sync.aligned.m16n8k16.row.col.f32.bf16.bf16.f32 " \
                    "{%0,%1,%2,%3}, {%4,%5,%6,%7}, {%8,%9}, {%0,%1,%2,%3};" \
                    : "+f"(acc[mi][ni][0]), "+f"(acc[mi][ni][1]), \
                      "+f"(acc[mi][ni][2]), "+f"(acc[mi][ni][3]) \
                    : "r"(af[sa][mi][0]), "r"(af[sa][mi][1]), \
                      "r"(af[sa][mi][2]), "r"(af[sa][mi][3]), \
                      "r"(bfr[sb][ni][0]), "r"(bfr[sb][ni][1])); \
    }

#define CP_ISSUE(b, k0) \
    _Pragma("unroll") \
    for (int u = 0; u < 2; u++) { \
        int seg = half*2 + u; \
        cpa16(&ASP(b,0,lrow,seg*8), Ab0 + (k0) + seg*8); \
        cpa16(&ASP(b,1,lrow,seg*8), Ab1 + (k0) + seg*8); \
        cpa16(&BSP(b,0,lrow,seg*8), Bb0 + (k0) + seg*8); \
        cpa16(&BSP(b,1,lrow,seg*8), Bb1 + (k0) + seg*8); \
    } \
    CP_COMMIT;

__device__ __forceinline__ void gemm_body_ca(
    const __nv_bfloat16* __restrict__ A0, const __nv_bfloat16* __restrict__ A1,
    const __nv_bfloat16* __restrict__ B0, const __nv_bfloat16* __restrict__ B1,
    const float* __restrict__ bias, float* __restrict__ Co, __nv_bfloat16* dyn) {
    const int tid = threadIdx.x, warp = tid >> 5, lane = tid & 31;
    const int g = lane >> 2, tg = lane & 3;
    const int i0 = blockIdx.x * 128, j0 = blockIdx.y * 128;
    const int wm = (warp & 1) * 64, wn = (warp >> 1) * 32;
    float acc[4][4][4];
    #pragma unroll
    for (int mi = 0; mi < 4; mi++)
        #pragma unroll
        for (int ni = 0; ni < 4; ni++)
            #pragma unroll
            for (int e = 0; e < 4; e++) acc[mi][ni][e] = 0.0f;
    const int lrow = tid >> 1, half = tid & 1;
    const __nv_bfloat16* Ab0 = A0 + (size_t)(i0 + lrow) * CC;
    const __nv_bfloat16* Ab1 = A1 + (size_t)(i0 + lrow) * CC;
    const __nv_bfloat16* Bb0 = B0 + (size_t)(j0 + lrow) * CC;
    const __nv_bfloat16* Bb1 = B1 + (size_t)(j0 + lrow) * CC;
    CP_ISSUE(0, 0)
    CP_WAIT0; __syncthreads();
    const int NCH = CC/32;
    for (int ci = 0; ci < NCH; ci++) {
        const int cur = ci & 1;
        if (ci + 1 < NCH) { CP_ISSUE(cur ^ 1, (ci+1)*32) }
        #pragma unroll
        for (int kk = 0; kk < 32; kk += 16) { MMA_FRAGS_P(cur) }
        CP_WAIT0; __syncthreads();
    }
    #pragma unroll
    for (int mi = 0; mi < 4; mi++) {
        int r0 = i0 + wm + mi*16 + g;
        #pragma unroll
        for (int ni = 0; ni < 4; ni++) {
            int c = j0 + wn + ni*8 + tg*2;
            float b0v = bias[c], b1v = bias[c+1];
            Co[(size_t)r0*CC + c]       = acc[mi][ni][0] + b0v;
            Co[(size_t)r0*CC + c+1]     = acc[mi][ni][1] + b1v;
            Co[(size_t)(r0+8)*CC + c]   = acc[mi][ni][2] + b0v;
            Co[(size_t)(r0+8)*CC + c+1] = acc[mi][ni][3] + b1v;
        }
    }
}

__global__ __launch_bounds__(256, 2) void k_gemm3(
    const float* bq, float* oq, const float* bk, float* ok,
    const float* bv, float* ov) {
    extern __shared__ __nv_bfloat16 dyn[];
    const int z = blockIdx.z;
    const __nv_bfloat16* A0 = g_sa0 + (size_t)z*RR*CC;
    const __nv_bfloat16* A1 = g_sa1 + (size_t)z*RR*CC;
    const __nv_bfloat16* B0 = g_sw0 + (size_t)z*CC*CC;
    const __nv_bfloat16* B1 = g_sw1 + (size_t)z*CC*CC;
    if (z == 0)      gemm_body_ca(A0, A1, B0, B1, bq, oq, dyn);
    else if (z == 1) gemm_body_ca(A0, A1, B0, B1, bk, ok, dyn);
    else             gemm_body_ca(A0, A1, B0, B1, bv, ov, dyn);
}

__global__ __launch_bounds__(256, 2) void k_gemm1(const float* bias, float* Co) {
    extern __shared__ __nv_bfloat16 dyn[];
    gemm_body_ca(g_sa0, g_sa1, g_sw0, g_sw1, bias, Co, dyn);
}

__global__ __launch_bounds__(256, 2) void k_simE_mma() {
    extern __shared__ __nv_bfloat16 dyn[];
    const int tid = threadIdx.x, warp = tid >> 5, lane = tid & 31;
    const int g = lane >> 2, tg = lane & 3;
    const int bb = blockIdx.z, m0 = blockIdx.x * 128, n0 = blockIdx.y * 128;
    const int wm = (warp & 1) * 64, wn = (warp >> 1) * 32;
    float acc[4][4][4];
    #pragma unroll
    for (int mi = 0; mi < 4; mi++)
        #pragma unroll
        for (int ni = 0; ni < 4; ni++)
            #pragma unroll
            for (int e = 0; e < 4; e++) acc[mi][ni][e] = 0.0f;
    const int lrow = tid >> 1, half = tid & 1;
    const __nv_bfloat16* Ab0 = g_ks0 + (size_t)(bb*MM + m0 + lrow) * CC;
    const __nv_bfloat16* Ab1 = g_ks1 + (size_t)(bb*MM + m0 + lrow) * CC;
    const __nv_bfloat16* Bb0 = g_qs0 + ((size_t)(n0 + lrow)*NB + bb) * CC;
    const __nv_bfloat16* Bb1 = g_qs1 + ((size_t)(n0 + lrow)*NB + bb) * CC;
    CP_ISSUE(0, 0)
    CP_WAIT0; __syncthreads();
    const int NCH = CC/32;
    for (int ci = 0; ci < NCH; ci++) {
        const int cur = ci & 1;
        if (ci + 1 < NCH) { CP_ISSUE(cur ^ 1, (ci+1)*32) }
        #pragma unroll
        for (int kk = 0; kk < 32; kk += 16) { MMA_FRAGS_P(cur) }
        CP_WAIT0; __syncthreads();
    }
    #pragma unroll
    for (int mi = 0; mi < 4; mi++) {
        int mA = m0 + wm + mi*16 + g;
        int mB = mA + 8;
        int mkA = g_maskb[bb*MM + mA], mkB = g_maskb[bb*MM + mB];
        size_t baseA = ((size_t)bb*MM + mA) * NQ;
        size_t baseB = ((size_t)bb*MM + mB) * NQ;
        #pragma unroll
        for (int ni = 0; ni < 4; ni++) {
            int c = n0 + wn + ni*8 + tg*2;
            float s0 = acc[mi][ni][0], s1 = acc[mi][ni][1];
            float s2 = acc[mi][ni][2], s3 = acc[mi][ni][3];
            g_sim[baseA + c]   = s0; g_sim[baseA + c+1] = s1;
            g_sim[baseB + c]   = s2; g_sim[baseB + c+1] = s3;
            float e0 = mkA ? expf((s0 - 1.0f) * EPS_INV) : 0.0f;
            float e1 = mkA ? expf((s1 - 1.0f) * EPS_INV) : 0.0f;
            float e2 = mkB ? expf((s2 - 1.0f) * EPS_INV) : 0.0f;
            float e3 = mkB ? expf((s3 - 1.0f) * EPS_INV) : 0.0f;
            g_E[baseA + c]   = e0; g_E[baseA + c+1] = e1;
            g_E[baseB + c]   = e2; g_E[baseB + c+1] = e3;
            g_Ebf[baseA + c]   = __float2bfloat16(e0);
            g_Ebf[baseA + c+1] = __float2bfloat16(e1);
            g_Ebf[baseB + c]   = __float2bfloat16(e2);
            g_Ebf[baseB + c+1] = __float2bfloat16(e3);
        }
    }
}

// HMMA TN xgemm (unchanged, static smem)
#define MMA_FRAGS_S \
    uint32_t af[2][4][4], bfr[2][4][2]; \
    _Pragma("unroll") \
    for (int s = 0; s < 2; s++) { \
        _Pragma("unroll") \
        for (int mi = 0; mi < 4; mi++) { \
            int r0 = wm + mi*16 + g; \
            af[s][mi][0] = *(const uint32_t*)&As[s][r0][kk + tg*2]; \
            af[s][mi][1] = *(const uint32_t*)&As[s][r0+8][kk + tg*2]; \
            af[s][mi][2] = *(const uint32_t*)&As[s][r0][kk + tg*2 + 8]; \
            af[s][mi][3] = *(const uint32_t*)&As[s][r0+8][kk + tg*2 + 8]; \
        } \
        _Pragma("unroll") \
        for (int ni = 0; ni < 4; ni++) { \
            int c0 = wn + ni*8 + g; \
            bfr[s][ni][0] = *(const uint32_t*)&Bs[s][c0][kk + tg*2]; \
            bfr[s][ni][1] = *(const uint32_t*)&Bs[s][c0][kk + tg*2 + 8]; \
        } \
    } \
    _Pragma("unroll") \
    for (int p = 0; p < 3; p++) { \
        const int sa = (p == 2) ? 1 : 0, sb = (p == 1) ? 1 : 0; \
        _Pragma("unroll") \
        for (int mi = 0; mi < 4; mi++) \
            _Pragma("unroll") \
            for (int ni = 0; ni < 4; ni++) \
                asm volatile( \
                    "mma.sync.aligned.m16n8k16.row.col.f32.bf16.bf16.f32 " \
                    "{%0,%1,%2,%3}, {%4,%5,%6,%7}, {%8,%9}, {%0,%1,%2,%3};" \
                    : "+f"(acc[mi][ni][0]), "+f"(acc[mi][ni][1]), \
                      "+f"(acc[mi][ni][2]), "+f"(acc[mi][ni][3]) \
                    : "r"(af[sa][mi][0]), "r"(af[sa][mi][1]), \
                      "r"(af[sa][mi][2]), "r"(af[sa][mi][3]), \
                      "r"(bfr[sb][ni][0]), "r"(bfr[sb][ni][1])); \
    }

__global__ __launch_bounds__(256) void k_xgemm_mma() {
    __shared__ __nv_bfloat16 As[2][128][SPAD];
    __shared__ __nv_bfloat16 Bs[2][128][SPAD];
    const int tid = threadIdx.x, warp = tid >> 5, lane = tid & 31;
    const int g = lane >> 2, tg = lane & 3;
    const int bb = blockIdx.z, n0 = blockIdx.x * 128, c0 = blockIdx.y * 128;
    const int wm = (warp & 1) * 64, wn = (warp >> 1) * 32;
    float acc[4][4][4];
    #pragma unroll
    for (int mi = 0; mi < 4; mi++)
        #pragma unroll
        for (int ni = 0; ni < 4; ni++)
            #pragma unroll
            for (int e = 0; e < 4; e++) acc[mi][ni][e] = 0.0f;
    const float* Eb = g_E + (size_t)bb*MM*NQ;
    const float* Vb = g_v + (size_t)bb*MM*CC;
    const int lm = tid & 31, lg = tid >> 5;
    for (int k0 = 0; k0 < MM; k0 += 32) {
        int m = k0 + lm;
        float am = g_a[bb*MM + m];
        #pragma unroll
        for (int j = 0; j < 4; j++) {
            int n = lg*16 + j*4;
            float4 ev = *(const float4*)(Eb + (size_t)m*NQ + n0 + n);
            float4 vv = *(const float4*)(Vb + (size_t)m*CC + c0 + n);
            vv.x *= am; vv.y *= am; vv.z *= am; vv.w *= am;
            float ee[4] = {ev.x, ev.y, ev.z, ev.w};
            float va[4] = {vv.x, vv.y, vv.z, vv.w};
            #pragma unroll
            for (int q = 0; q < 4; q++) {
                __nv_bfloat16 h = __float2bfloat16(ee[q]);
                As[0][n + q][lm] = h;
                As[1][n + q][lm] = __float2bfloat16(ee[q] - __bfloat162float(h));
                __nv_bfloat16 hv = __float2bfloat16(va[q]);
                Bs[0][n + q][lm] = hv;
                Bs[1][n + q][lm] = __float2bfloat16(va[q] - __bfloat162float(hv));
            }
        }
        __syncthreads();
        #pragma unroll
        for (int kk = 0; kk < 32; kk += 16) { MMA_FRAGS_S }
        __syncthreads();
    }
    #pragma unroll
    for (int mi = 0; mi < 4; mi++) {
        int nA = n0 + wm + mi*16 + g;
        int nB = nA + 8;
        float bnA = g_bfin[bb*NQ + nA], bnB = g_bfin[bb*NQ + nB];
        #pragma unroll
        for (int ni = 0; ni < 4; ni++) {
            int c = c0 + wn + ni*8 + tg*2;
            g_x[((size_t)nA*NB + bb)*CC + c]   = acc[mi][ni][0] * bnA;
            g_x[((size_t)nA*NB + bb)*CC + c+1] = acc[mi][ni][1] * bnA;
            g_x[((size_t)nB*NB + bb)*CC + c]   = acc[mi][ni][2] * bnB;
            g_x[((size_t)nB*NB + bb)*CC + c+1] = acc[mi][ni][3] * bnB;
        }
    }
}

// persistent Sinkhorn: 512 threads (16 warps x 4 rows), smem E, atomic barrier, fused attn
#define SINK_SMEM (64*NQ*2 + 16*NQ*4)
__global__ __launch_bounds__(512) void k_sink_pers(float* attn_out) {
    extern __shared__ char dsm[];
    __nv_bfloat16* Es = (__nv_bfloat16*)dsm;
    float* shred = (float*)(dsm + 64*NQ*2);
    const int blk = blockIdx.x, bb = blk >> 4, rb = blk & 15;
    const int tid = threadIdx.x, warp = tid >> 5, lane = tid & 31;
    const int col2 = tid * 2;
    {
        const uint4* src = (const uint4*)(g_Ebf + ((size_t)bb*MM + rb*64) * NQ);
        uint4* dst = (uint4*)Es;
        for (int i = tid; i < 64*NQ/8; i += 512) dst[i] = src[i];
    }
    __syncthreads();
    float bv[32];
    #pragma unroll
    for (int q = 0; q < 32; q++) bv[q] = 1.0f;
    float a_loc[4];
    #pragma unroll
    for (int q = 0; q < 4; q++) a_loc[q] = 0.0f;
    for (int it = 1; it <= NITER; it++) {
        float cacc[32];
        #pragma unroll
        for (int q = 0; q < 32; q++) cacc[q] = 0.0f;
        #pragma unroll
        for (int rr = 0; rr < 4; rr++) {
            int lr = warp*4 + rr;
            int m = rb*64 + lr;
            if (!g_maskb[bb*MM + m]) {
                if (it == NITER && lane == 0) g_a[bb*MM + m] = 0.0f;
                continue;
            }
            const __nv_bfloat16* er = Es + (size_t)lr * NQ;
            float e[32], s = 0.0f;
            #pragma unroll
            for (int g = 0; g < 8; g++) {
                uint2 w = *(const uint2*)(er + g*128 + lane*4);
                __nv_bfloat162 p0 = *(__nv_bfloat162*)&w.x;
                __nv_bfloat162 p1 = *(__nv_bfloat162*)&w.y;
                e[g*4+0] = __bfloat162float(__low2bfloat16(p0));
                e[g*4+1] = __bfloat162float(__high2bfloat16(p0));
                e[g*4+2] = __bfloat162float(__low2bfloat16(p1));
                e[g*4+3] = __bfloat162float(__high2bfloat16(p1));
                s += e[g*4+0]*bv[g*4+0] + e[g*4+1]*bv[g*4+1]
                   + e[g*4+2]*bv[g*4+2] + e[g*4+3]*bv[g*4+3];
            }
            #pragma unroll
            for (int o = 16; o; o >>= 1) s += __shfl_xor_sync(0xffffffffu, s, o);
            float a = g_mu[bb*MM + m] / s;
            if (it == NITER) {
                a_loc[rr] = a;
                if (lane == 0) g_a[bb*MM + m] = a;
            }
            #pragma unroll
            for (int q = 0; q < 32; q++) cacc[q] += a * e[q];
        }
        #pragma unroll
        for (int g = 0; g < 8; g++)
            *(float4*)&shred[warp*1024 + g*128 + lane*4] =
                make_float4(cacc[g*4], cacc[g*4+1], cacc[g*4+2], cacc[g*4+3]);
        __syncthreads();
        float s0 = 0.0f, s1 = 0.0f;
        #pragma unroll
        for (int w = 0; w < 16; w++) {
            float2 v = *(const float2*)&shred[w*1024 + col2];
            s0 += v.x; s1 += v.y;
        }
        *(float2*)&g_cpart[(size_t)blk*NQ + col2] = make_float2(s0, s1);
        __threadfence();
        __syncthreads();
        if (tid == 0) {
            atomicAdd(&g_bar8[bb], 1u);
            unsigned int target = (unsigned int)it * 16u;
            while (atomicAdd(&g_bar8[bb], 0u) < target) __nanosleep(64);
        }
        __syncthreads();
        __threadfence();
        if (it < NITER) {
            float c0 = 0.0f, c1 = 0.0f;
            #pragma unroll
            for (int w = 0; w < 16; w++) {
                float2 v = *(const float2*)&g_cpart[(size_t)(bb*16 + w)*NQ + col2];
                c0 += v.x; c1 += v.y;
            }
            shred[col2+0] = NU_P / c0; shred[col2+1] = NU_P / c1;
            __syncthreads();
            #pragma unroll
            for (int g = 0; g < 8; g++) {
                float4 v = *(const float4*)&shred[g*128 + lane*4];
                bv[g*4+0]=v.x; bv[g*4+1]=v.y; bv[g*4+2]=v.z; bv[g*4+3]=v.w;
            }
            __syncthreads();
        }
    }
    {
        float c0 = 0.0f, c1 = 0.0f;
        #pragma unroll
        for (int w = 0; w < 16; w++) {
            float2 v = *(const float2*)&g_cpart[(size_t)(bb*16 + w)*NQ + col2];
            c0 += v.x; c1 += v.y;
        }
        float b0 = NU_P / c0, b1 = NU_P / c1;
        shred[col2+0] = b0; shred[col2+1] = b1;
        if (rb == 0) {
            g_bfin[bb*NQ+col2+0] = b0; g_bfin[bb*NQ+col2+1] = b1;
        }
    }
    __syncthreads();
    if (attn_out) {
        #pragma unroll
        for (int rr = 0; rr < 4; rr++) {
            int lr = warp*4 + rr;
            int m = rb*64 + lr;
            float aL = a_loc[rr];
            float s = 0.0f;
            if (aL != 0.0f) {
                const float* S = g_sim + ((size_t)bb*MM + m) * NQ;
                const __nv_bfloat16* er = Es + (size_t)lr * NQ;
                #pragma unroll
                for (int g = 0; g < 8; g++) {
                    int n = g*128 + lane*4;
                    float4 sv = *(const float4*)(S + n);
                    uint2 w = *(const uint2*)(er + n);
                    __nv_bfloat162 p0 = *(__nv_bfloat162*)&w.x;
                    __nv_bfloat162 p1 = *(__nv_bfloat162*)&w.y;
                    float4 bvv = *(const float4*)&shred[n];
                    s += sv.x * __bfloat162float(__low2bfloat16(p0))  * bvv.x
                       + sv.y * __bfloat162float(__high2bfloat16(p0)) * bvv.y
                       + sv.z * __bfloat162float(__low2bfloat16(p1))  * bvv.z
                       + sv.w * __bfloat162float(__high2bfloat16(p1)) * bvv.w;
                }
                #pragma unroll
                for (int o = 16; o; o >>= 1) s += __shfl_xor_sync(0xffffffffu, s, o);
            }
            if (lane == 0) attn_out[bb*MM + m] = 1048576.0f * aL * s;
        }
    }
}

extern "C" void kernel_launch(void* const* d_in, const int* in_sizes, int n_in,
                              void* d_out, int out_size) {
    const float* xq = (const float*)d_in[0];
    const float* xk = (const float*)d_in[1];
    const float* xv = (const float*)d_in[2];
    const void*  mk = d_in[3];
    const float* Wq = (const float*)d_in[4];
    const float* bq = (const float*)d_in[5];
    const float* Wk = (const float*)d_in[6];
    const float* bk = (const float*)d_in[7];
    const float* Wv = (const float*)d_in[8];
    const float* bv = (const float*)d_in[9];
    const float* Wp = (const float*)d_in[10];
    const float* bp = (const float*)d_in[11];
    float *qp, *kp, *vp, *xp;
    __nv_bfloat16 *q0, *q1, *ks0, *ks1, *sa0, *sa1, *sw0, *sw1;
    cudaGetSymbolAddress((void**)&qp, g_q);
    cudaGetSymbolAddress((void**)&kp, g_k);
    cudaGetSymbolAddress((void**)&vp, g_v);
    cudaGetSymbolAddress((void**)&xp, g_x);
    cudaGetSymbolAddress((void**)&q0, g_qs0);
    cudaGetSymbolAddress((void**)&q1, g_qs1);
    cudaGetSymbolAddress((void**)&ks0, g_ks0);
    cudaGetSymbolAddress((void**)&ks1, g_ks1);
    cudaGetSymbolAddress((void**)&sa0, g_sa0);
    cudaGetSymbolAddress((void**)&sa1, g_sa1);
    cudaGetSymbolAddress((void**)&sw0, g_sw0);
    cudaGetSymbolAddress((void**)&sw1, g_sw1);
    cudaFuncSetAttribute(k_gemm3, cudaFuncAttributeMaxDynamicSharedMemorySize, DYN_BYTES);
    cudaFuncSetAttribute(k_gemm1, cudaFuncAttributeMaxDynamicSharedMemorySize, DYN_BYTES);
    cudaFuncSetAttribute(k_simE_mma, cudaFuncAttributeMaxDynamicSharedMemorySize, DYN_BYTES);
    cudaFuncSetAttribute(k_sink_pers, cudaFuncAttributeMaxDynamicSharedMemorySize, SINK_SMEM);

    k_detect<<<1, 256>>>((const unsigned char*)mk);
    k_counts<<<NB, 256>>>(mk);
    k_init<<<(RR + 255)/256, 256>>>(mk);

    {
        long long tot = 3LL*RR*CC/4 + 3LL*CC*CC/4;
        k_splitmulti<<<(int)((tot + 255)/256), 256>>>(xq, xk, xv, Wq, Wk, Wv);
    }
    k_gemm3<<<dim3(RR/128, CC/128, 3), 256, DYN_BYTES>>>(bq, qp, bk, kp, bv, vp);

    k_l2split<<<RR, 256>>>(qp, q0, q1);
    k_l2split<<<RR, 256>>>(kp, ks0, ks1);

    k_simE_mma<<<dim3(MM/128, NQ/128, NB), 256, DYN_BYTES>>>();

    float* attn_ptr = (out_size >= RR*CC + RR) ? ((float*)d_out + (size_t)RR*CC) : nullptr;
    k_sink_pers<<<128, 512, SINK_SMEM>>>(attn_ptr);

    k_xgemm_mma<<<dim3(NQ/128, CC/128, NB), 256>>>();

    k_split2v<<<(RR*CC/4 + 255)/256, 256>>>(xp, sa0, sa1, RR*CC/4);
    k_split2v<<<(CC*CC/4 + 255)/256, 256>>>(Wp, sw0, sw1, CC*CC/4);
    k_gemm1<<<dim3(RR/128, CC/128), 256, DYN_BYTES>>>(bp, (float*)d_out);
}